// round 12
// baseline (speedup 1.0000x reference)
#include <cuda_runtime.h>
#include <cuda_fp16.h>
#include <math.h>
#include <stdint.h>

#define SEQ   1024
#define BATCH 4
#define DM    1024
#define NH    16
#define HD    64
#define NPOS  1000
#define NTOK  (SEQ*BATCH)   // 4096
#define NHB   (NH*BATCH)    // 64

// ---------------------------------------------------------------------------
// Device scratch (no runtime allocation allowed) — all fp16
// ---------------------------------------------------------------------------
__device__ __align__(16) __half gx[NTOK*DM];
__device__ __align__(16) __half gw[4*DM*DM];          // WqT,WkT,WvT,WoT [n][k]
__device__ __align__(16) __half gpet[SEQ*HD];         // peT [n pad][d]
__device__ __align__(16) __half gq[NHB*SEQ*HD];
__device__ __align__(16) __half gk[NHB*SEQ*HD];
__device__ __align__(16) __half gv[NHB*SEQ*HD];
__device__ __align__(16) __half gvt[NHB*HD*SEQ];      // vT [hb][d][t]
__device__ __align__(16) __half gp[(size_t)NHB*SEQ*SEQ];        // probs
__device__ __align__(16) __half gctx[NTOK*DM];

// ---------------------------------------------------------------------------
// Helpers (baseline PTX only)
// ---------------------------------------------------------------------------
__device__ __forceinline__ uint32_t smem_u32(const void* p) {
    uint32_t a;
    asm("{ .reg .u64 t; cvta.to.shared.u64 t, %1; cvt.u32.u64 %0, t; }"
        : "=r"(a) : "l"(p));
    return a;
}
__device__ __forceinline__ void ldm4(uint32_t* r, uint32_t addr) {
    asm volatile("ldmatrix.sync.aligned.m8n8.x4.shared.b16 {%0,%1,%2,%3}, [%4];"
        : "=r"(r[0]), "=r"(r[1]), "=r"(r[2]), "=r"(r[3]) : "r"(addr));
}
__device__ __forceinline__ void mma_f16(float* c, const uint32_t* a,
                                        const uint32_t* b) {
    asm volatile(
        "mma.sync.aligned.m16n8k16.row.col.f32.f16.f16.f32 "
        "{%0,%1,%2,%3}, {%4,%5,%6,%7}, {%8,%9}, {%0,%1,%2,%3};"
        : "+f"(c[0]), "+f"(c[1]), "+f"(c[2]), "+f"(c[3])
        : "r"(a[0]), "r"(a[1]), "r"(a[2]), "r"(a[3]), "r"(b[0]), "r"(b[1]));
}
__device__ __forceinline__ void cp16(uint32_t dst, const void* src) {
    asm volatile("cp.async.ca.shared.global [%0], [%1], 16;"
                 :: "r"(dst), "l"(src));
}
#define CP_COMMIT asm volatile("cp.async.commit_group;" ::: "memory")
template<int N>
__device__ __forceinline__ void cp_wait() {
    asm volatile("cp.async.wait_group %0;" :: "n"(N) : "memory");
}

__device__ __forceinline__ float sigmoidf_(float x) {
    return 1.0f / (1.0f + __expf(-x));
}

// ---------------------------------------------------------------------------
// Stage ROWSx32 fp16 K-major subtile via cp.async; pitch 80B.
// ---------------------------------------------------------------------------
template<int ROWS>
__device__ __forceinline__ void stage_cp(const __half* __restrict__ src, int ld,
                                         uint32_t smem_byte, int tid)
{
    #pragma unroll
    for (int it = 0; it < ROWS / 64; it++) {
        int q = tid + it * 256;
        int row = q >> 2, ch = q & 3;
        cp16(smem_byte + row * 80 + ch * 16, src + (size_t)row * ld + ch * 8);
    }
}

// ---------------------------------------------------------------------------
// Core: C[128 x NTILE*16] += A[128 x ktot] · B[NTILE*16 x ktot]^T
// fp16 single-product, fp32 accum. 64-k chunks, STAGES-deep cp.async ring,
// one sync per 64-k chunk. 8 warps as 4(m) x 2(n).
// ---------------------------------------------------------------------------
template<int NTILE, int STAGES>
__device__ __forceinline__ void mma_core(
    const __half* A, int a_ld, const __half* B, int b_ld,
    int ktot, float acc[2][NTILE][4], char* smem)
{
    const int tid = threadIdx.x;
    const int warp = tid >> 5, lane = tid & 31;
    const int wm = warp >> 1, wn = warp & 1;
    constexpr int NROWS = NTILE * 16;
    constexpr int TA32 = 128 * 80;
    constexpr int TB32 = NROWS * 80;
    constexpr int TA = 2 * TA32;
    constexpr int TB = 2 * TB32;
    constexpr int STAGE = TA + TB;
    const uint32_t sb = smem_u32(smem);
    const int nch = ktot / 64;

    #pragma unroll
    for (int s = 0; s < STAGES - 1; s++) {
        if (s < nch) {
            uint32_t nb = sb + s * STAGE;
            stage_cp<128>(A + s * 64, a_ld, nb, tid);
            stage_cp<128>(A + s * 64 + 32, a_ld, nb + TA32, tid);
            stage_cp<NROWS>(B + s * 64, b_ld, nb + TA, tid);
            stage_cp<NROWS>(B + s * 64 + 32, b_ld, nb + TA + TB32, tid);
        }
        CP_COMMIT;
    }

    for (int c = 0; c < nch; c++) {
        cp_wait<STAGES - 2>();
        __syncthreads();
        int pf = c + STAGES - 1;
        if (pf < nch) {
            uint32_t nb = sb + (pf % STAGES) * STAGE;
            stage_cp<128>(A + pf * 64, a_ld, nb, tid);
            stage_cp<128>(A + pf * 64 + 32, a_ld, nb + TA32, tid);
            stage_cp<NROWS>(B + pf * 64, b_ld, nb + TA, tid);
            stage_cp<NROWS>(B + pf * 64 + 32, b_ld, nb + TA + TB32, tid);
        }
        CP_COMMIT;

        const uint32_t cb = sb + (c % STAGES) * STAGE;
        #pragma unroll
        for (int sub = 0; sub < 2; sub++) {
            const uint32_t ca = cb + sub * TA32;
            const uint32_t cbB = cb + TA + sub * TB32;
            #pragma unroll
            for (int kk = 0; kk < 32; kk += 16) {
                uint32_t ah[2][4];
                #pragma unroll
                for (int tm = 0; tm < 2; tm++) {
                    int r = wm * 32 + tm * 16 + ((lane >> 3) & 1) * 8 + (lane & 7);
                    int cc = kk + ((lane >> 4) & 1) * 8;
                    ldm4(ah[tm], ca + (uint32_t)(r * 80 + cc * 2));
                }
                #pragma unroll
                for (int p = 0; p < NTILE / 2; p++) {
                    uint32_t bh[4];
                    int r = wn * NTILE * 8 + p * 16 + ((lane >> 4) & 1) * 8 + (lane & 7);
                    int cc = kk + ((lane >> 3) & 1) * 8;
                    ldm4(bh, cbB + (uint32_t)(r * 80 + cc * 2));
                    #pragma unroll
                    for (int tm = 0; tm < 2; tm++) {
                        mma_f16(acc[tm][2 * p],     ah[tm], bh);
                        mma_f16(acc[tm][2 * p + 1], ah[tm], bh + 2);
                    }
                }
            }
        }
    }
}

#define SMEM_N128 (2 * (2 * 128 * 80 + 2 * 128 * 80))   // 81920 (2-stage, N128)
#define SMEM_AV   (3 * (2 * 128 * 80 + 2 * 64 * 80))    // 92160 (3-stage, N64)

// ---------------------------------------------------------------------------
// Prologue conversion kernels
// ---------------------------------------------------------------------------
__global__ __launch_bounds__(256) void convert_x(const float* __restrict__ x)
{
    int i = (blockIdx.x * 256 + threadIdx.x) * 4;
    float4 v = *(const float4*)(x + i);
    *(__half2*)(gx + i)     = __floats2half2_rn(v.x, v.y);
    *(__half2*)(gx + i + 2) = __floats2half2_rn(v.z, v.w);
}

// z = 0..3: W transposes; z = 4: pe transpose (y < 2 active)
__global__ __launch_bounds__(256) void transpose_wpe(
    const float* __restrict__ Wq, const float* __restrict__ Wk,
    const float* __restrict__ Wv, const float* __restrict__ Wo,
    const float* __restrict__ pe)
{
    __shared__ float t[32][33];
    int tx = threadIdx.x & 31, ty = threadIdx.x >> 5;
    int bx = blockIdx.x * 32, by = blockIdx.y * 32;
    int z = blockIdx.z;

    if (z < 4) {
        const float* W = (z == 0) ? Wq : (z == 1) ? Wk : (z == 2) ? Wv : Wo;
        size_t base = (size_t)z * DM * DM;
        #pragma unroll
        for (int j = 0; j < 4; j++)
            t[ty + 8 * j][tx] = W[(size_t)(by + ty + 8 * j) * DM + bx + tx];
        __syncthreads();
        #pragma unroll
        for (int j = 0; j < 4; j++)
            gw[base + (size_t)(bx + ty + 8 * j) * DM + by + tx] =
                __float2half_rn(t[tx][ty + 8 * j]);
    } else {
        if (by >= HD) return;
        #pragma unroll
        for (int j = 0; j < 4; j++) {
            int d = by + ty + 8 * j, n = bx + tx;
            t[ty + 8 * j][tx] = (n < NPOS) ? pe[(size_t)d * NPOS + n] : 0.0f;
        }
        __syncthreads();
        #pragma unroll
        for (int j = 0; j < 4; j++)
            gpet[(size_t)(bx + ty + 8 * j) * HD + by + tx] =
                __float2half_rn(t[tx][ty + 8 * j]);
    }
}

__global__ __launch_bounds__(256) void transpose_v()
{
    __shared__ __half t[32][40];
    int hb = blockIdx.z;
    const __half* V = gv + (size_t)hb * SEQ * HD;
    size_t base = (size_t)hb * HD * SEQ;
    int tx = threadIdx.x & 31, ty = threadIdx.x >> 5;
    int bx = blockIdx.x * 32, by = blockIdx.y * 32;   // bx: t, by: d
    #pragma unroll
    for (int j = 0; j < 4; j++)
        t[ty + 8 * j][tx] = V[(size_t)(bx + ty + 8 * j) * HD + by + tx];
    __syncthreads();
    #pragma unroll
    for (int j = 0; j < 4; j++)
        gvt[base + (size_t)(by + ty + 8 * j) * SEQ + bx + tx] = t[tx][ty + 8 * j];
}

// ---------------------------------------------------------------------------
// K1: QKV projections (scatter to head layout, +bias) -> fp16 q,k,v
// ---------------------------------------------------------------------------
__global__ __launch_bounds__(256, 2) void qkv_mma(
    const float* __restrict__ bq, const float* __restrict__ bk,
    const float* __restrict__ bv)
{
    extern __shared__ char smem[];
    const int tid = threadIdx.x;
    const int warp = tid >> 5, lane = tid & 31;
    const int wm = warp >> 1, wn = warp & 1;
    const int n0b = blockIdx.x * 128, m0b = blockIdx.y * 128, z = blockIdx.z;
    const float* bias = (z == 0) ? bq : (z == 1) ? bk : bv;
    __half* out = (z == 0) ? gq : (z == 1) ? gk : gv;

    float acc[2][8][4] = {};
    mma_core<8, 2>(gx + (size_t)m0b * DM, DM,
                   gw + (size_t)z * DM * DM + (size_t)n0b * DM, DM,
                   DM, acc, smem);

    #pragma unroll
    for (int tm = 0; tm < 2; tm++) {
        #pragma unroll
        for (int tn = 0; tn < 8; tn++) {
            int c = n0b + wn * 64 + tn * 8 + 2 * (lane & 3);
            int h = c >> 6, d = c & 63;
            float2 bb = *(const float2*)(bias + c);
            #pragma unroll
            for (int half_ = 0; half_ < 2; half_++) {
                int m = m0b + wm * 32 + tm * 16 + (lane >> 2) + half_ * 8;
                int s = m >> 2, b_ = m & 3;
                __half2 v = __floats2half2_rn(acc[tm][tn][2 * half_ + 0] + bb.x,
                                              acc[tm][tn][2 * half_ + 1] + bb.y);
                *(__half2*)(out + ((size_t)(h * BATCH + b_) * SEQ + s) * HD + d) = v;
            }
        }
    }
}

// ---------------------------------------------------------------------------
// K2 (fused): QK^T + Q·PE + CoPE + softmax per (hb, 32 q-rows).
// logits/li live only in smem; probs written to gp.
// 16 B-chunks (8 from K, 8 from PE) streamed through a 3-buffer cp.async ring.
// 8 warps as 2(m:16) x 4(n:32) per 128-col chunk.
// ---------------------------------------------------------------------------
#define PLB 2096                          // smem row pitch bytes (16B-aligned, conflict-spread)
#define FQ_SQ   0                         // Q: 2 subtiles x 32 x 80 = 5120
#define FQ_SB   5120                      // B ring: 3 x 20480 = 61440
#define FQ_SLOG 66560                     // 32 x PLB = 67072
#define FQ_SLI  (FQ_SLOG + 32 * PLB)      // 133632
#define FQ_SMEM (FQ_SLOG + 64 * PLB)      // 200704

__global__ __launch_bounds__(256, 1) void qkcope()
{
    extern __shared__ char smem[];
    const int tid = threadIdx.x;
    const int warp = tid >> 5, lane = tid & 31;
    const int wm = warp >> 2, wn = warp & 3;
    const int m0b = blockIdx.x * 32, hb = blockIdx.y;
    const uint32_t sb = smem_u32(smem);

    const __half* Q = gq + (size_t)hb * SEQ * HD + (size_t)m0b * HD;
    const __half* K = gk + (size_t)hb * SEQ * HD;

    // prologue: stage Q (both 32-k subtiles) + B chunks 0,1
    {
        int q = tid & 127, row = q >> 2, ch = q & 3;
        int sub = tid >> 7;
        cp16(sb + FQ_SQ + sub * 2560 + row * 80 + ch * 16,
             Q + (size_t)row * HD + sub * 32 + ch * 8);
    }
    stage_cp<128>(K, HD, sb + FQ_SB, tid);
    stage_cp<128>(K + 32, HD, sb + FQ_SB + 10240, tid);
    CP_COMMIT;
    stage_cp<128>(K + (size_t)128 * HD, HD, sb + FQ_SB + 20480, tid);
    stage_cp<128>(K + (size_t)128 * HD + 32, HD, sb + FQ_SB + 20480 + 10240, tid);
    CP_COMMIT;

    uint32_t af[2][2][4];
    bool a_loaded = false;

    for (int c = 0; c < 16; c++) {
        cp_wait<1>();
        __syncthreads();
        int pf = c + 2;
        if (pf < 16) {
            const __half* Bsrc = (pf < 8)
                ? K + (size_t)pf * 128 * HD
                : gpet + (size_t)(pf - 8) * 128 * HD;
            uint32_t nb = sb + FQ_SB + (pf % 3) * 20480;
            stage_cp<128>(Bsrc, HD, nb, tid);
            stage_cp<128>(Bsrc + 32, HD, nb + 10240, tid);
        }
        CP_COMMIT;

        if (!a_loaded) {           // Q resident after first wait; hoist fragments
            a_loaded = true;
            #pragma unroll
            for (int sub = 0; sub < 2; sub++)
                #pragma unroll
                for (int kx = 0; kx < 2; kx++) {
                    int r = wm * 16 + ((lane >> 3) & 1) * 8 + (lane & 7);
                    int cc = kx * 16 + ((lane >> 4) & 1) * 8;
                    ldm4(af[sub][kx],
                         sb + FQ_SQ + sub * 2560 + (uint32_t)(r * 80 + cc * 2));
                }
        }

        float acc[4][4] = {};
        const uint32_t bbuf = sb + FQ_SB + (c % 3) * 20480;
        #pragma unroll
        for (int sub = 0; sub < 2; sub++) {
            #pragma unroll
            for (int kx = 0; kx < 2; kx++) {
                #pragma unroll
                for (int p = 0; p < 2; p++) {
                    uint32_t bh[4];
                    int r = wn * 32 + p * 16 + ((lane >> 4) & 1) * 8 + (lane & 7);
                    int cc = kx * 16 + ((lane >> 3) & 1) * 8;
                    ldm4(bh, bbuf + sub * 10240 + (uint32_t)(r * 80 + cc * 2));
                    mma_f16(acc[2 * p],     af[sub][kx], bh);
                    mma_f16(acc[2 * p + 1], af[sub][kx], bh + 2);
                }
            }
        }

        const float scale = (c < 8) ? 0.125f : 1.0f;
        char* dst = smem + ((c < 8) ? FQ_SLOG : FQ_SLI);
        int colchunk = (c & 7) * 128;
        #pragma unroll
        for (int tn = 0; tn < 4; tn++) {
            int col = colchunk + wn * 32 + tn * 8 + 2 * (lane & 3);
            #pragma unroll
            for (int half_ = 0; half_ < 2; half_++) {
                int row = wm * 16 + (lane >> 2) + half_ * 8;
                __half2 v = __floats2half2_rn(acc[tn][2 * half_ + 0] * scale,
                                              acc[tn][2 * half_ + 1] * scale);
                *(__half2*)(dst + row * PLB + col * 2) = v;
            }
        }
    }
    __syncthreads();

    // ---- CoPE + softmax, warp per 4 rows; probs -> gp ----
    for (int rr = 0; rr < 4; rr++) {
        int row = warp * 4 + rr;
        char* lrow = smem + FQ_SLOG + row * PLB;
        const char* lirow = smem + FQ_SLI + row * PLB;

        float l[4][8];
        float carry = 0.f, mx = -INFINITY;
        for (int seg = 3; seg >= 0; seg--) {
            int e0 = seg * 256 + lane * 8;
            uint4 u = *(const uint4*)(lrow + e0 * 2);
            const __half2* hp = (const __half2*)&u;
            #pragma unroll
            for (int i = 0; i < 4; i++) {
                float2 f = __half22float2(hp[i]);
                l[seg][2 * i + 0] = f.x;
                l[seg][2 * i + 1] = f.y;
            }
            float su[8];
            {
                float g = sigmoidf_(l[seg][7]); su[7] = g;
                #pragma unroll
                for (int j = 6; j >= 0; j--) su[j] = su[j + 1] + sigmoidf_(l[seg][j]);
            }
            float v = su[0];
            #pragma unroll
            for (int off = 1; off < 32; off <<= 1) {
                float n = __shfl_down_sync(0xffffffffu, v, off);
                if (lane + off < 32) v += n;
            }
            float tot = __shfl_sync(0xffffffffu, v, 0);
            float basev = carry + (v - su[0]);
            #pragma unroll
            for (int j = 0; j < 8; j++) {
                float p = fminf(basev + su[j], 999.0f);
                float pf = floorf(p);
                float w = p - pf;
                int fi = (int)pf;
                int ci = (int)ceilf(p);
                float lf = __half2float(*(const __half*)(lirow + fi * 2));
                float lc = __half2float(*(const __half*)(lirow + ci * 2));
                l[seg][j] += lc * w + lf * (1.0f - w);
                mx = fmaxf(mx, l[seg][j]);
            }
            carry += tot;
        }
        #pragma unroll
        for (int off = 16; off; off >>= 1)
            mx = fmaxf(mx, __shfl_xor_sync(0xffffffffu, mx, off));
        float sum = 0.f;
        #pragma unroll
        for (int seg = 0; seg < 4; seg++)
            #pragma unroll
            for (int j = 0; j < 8; j++) {
                l[seg][j] = __expf(l[seg][j] - mx);
                sum += l[seg][j];
            }
        #pragma unroll
        for (int off = 16; off; off >>= 1)
            sum += __shfl_xor_sync(0xffffffffu, sum, off);
        float inv = 1.0f / sum;

        __half* gpr = gp + ((size_t)hb << 20) + (size_t)(m0b + row) * SEQ;
        #pragma unroll
        for (int seg = 0; seg < 4; seg++) {
            union { __half2 h2[4]; uint4 u; } pv;
            #pragma unroll
            for (int i = 0; i < 4; i++)
                pv.h2[i] = __floats2half2_rn(l[seg][2 * i] * inv,
                                             l[seg][2 * i + 1] * inv);
            *(uint4*)(gpr + seg * 256 + lane * 8) = pv.u;
        }
    }
}

// ---------------------------------------------------------------------------
// K5: ctx = attn · V per (h,b). N = 64 -> fp16 ctx (3-stage, 64-k chunks)
// ---------------------------------------------------------------------------
__global__ __launch_bounds__(256, 2) void av_mma()
{
    extern __shared__ char smem[];
    const int tid = threadIdx.x;
    const int warp = tid >> 5, lane = tid & 31;
    const int wm = warp >> 1, wn = warp & 1;
    const int m0b = blockIdx.x * 128, hb = blockIdx.y;
    const int h = hb >> 2, b_ = hb & 3;

    float acc[2][4][4] = {};
    mma_core<4, 3>(gp + ((size_t)hb << 20) + (size_t)m0b * SEQ, SEQ,
                   gvt + (size_t)hb * HD * SEQ, SEQ,
                   SEQ, acc, smem);

    #pragma unroll
    for (int tm = 0; tm < 2; tm++) {
        #pragma unroll
        for (int tn = 0; tn < 4; tn++) {
            int d = wn * 32 + tn * 8 + 2 * (lane & 3);
            #pragma unroll
            for (int half_ = 0; half_ < 2; half_++) {
                int s = m0b + wm * 32 + tm * 16 + (lane >> 2) + half_ * 8;
                __half2 v = __floats2half2_rn(acc[tm][tn][2 * half_ + 0],
                                              acc[tm][tn][2 * half_ + 1]);
                *(__half2*)(gctx + ((size_t)s * BATCH + b_) * DM + h * HD + d) = v;
            }
        }
    }
}

// ---------------------------------------------------------------------------
// K6: output projection (+bias) -> fp32 out
// ---------------------------------------------------------------------------
__global__ __launch_bounds__(256, 2) void out_mma(const float* __restrict__ bo,
                                                  float* __restrict__ out)
{
    extern __shared__ char smem[];
    const int tid = threadIdx.x;
    const int warp = tid >> 5, lane = tid & 31;
    const int wm = warp >> 1, wn = warp & 1;
    const int n0b = blockIdx.x * 128, m0b = blockIdx.y * 128;

    float acc[2][8][4] = {};
    mma_core<8, 2>(gctx + (size_t)m0b * DM, DM,
                   gw + (size_t)3 * DM * DM + (size_t)n0b * DM, DM,
                   DM, acc, smem);

    #pragma unroll
    for (int tm = 0; tm < 2; tm++) {
        #pragma unroll
        for (int tn = 0; tn < 8; tn++) {
            int c = n0b + wn * 64 + tn * 8 + 2 * (lane & 3);
            float2 bb = *(const float2*)(bo + c);
            #pragma unroll
            for (int half_ = 0; half_ < 2; half_++) {
                int m = m0b + wm * 32 + tm * 16 + (lane >> 2) + half_ * 8;
                float2 v;
                v.x = acc[tm][tn][2 * half_ + 0] + bb.x;
                v.y = acc[tm][tn][2 * half_ + 1] + bb.y;
                *(float2*)(out + (size_t)m * DM + c) = v;
            }
        }
    }
}

// ---------------------------------------------------------------------------
extern "C" void kernel_launch(void* const* d_in, const int* in_sizes, int n_in,
                              void* d_out, int out_size)
{
    const float* x  = (const float*)d_in[0];
    const float* Wq = (const float*)d_in[1];
    const float* bq = (const float*)d_in[2];
    const float* Wk = (const float*)d_in[3];
    const float* bk = (const float*)d_in[4];
    const float* Wv = (const float*)d_in[5];
    const float* bv = (const float*)d_in[6];
    const float* Wo = (const float*)d_in[7];
    const float* bo = (const float*)d_in[8];
    const float* pe = (const float*)d_in[9];
    float* out = (float*)d_out;

    cudaFuncSetAttribute(qkv_mma, cudaFuncAttributeMaxDynamicSharedMemorySize, SMEM_N128);
    cudaFuncSetAttribute(out_mma, cudaFuncAttributeMaxDynamicSharedMemorySize, SMEM_N128);
    cudaFuncSetAttribute(av_mma,  cudaFuncAttributeMaxDynamicSharedMemorySize, SMEM_AV);
    cudaFuncSetAttribute(qkcope,  cudaFuncAttributeMaxDynamicSharedMemorySize, FQ_SMEM);

    convert_x<<<NTOK * DM / 1024, 256>>>(x);
    transpose_wpe<<<dim3(DM / 32, DM / 32, 5), 256>>>(Wq, Wk, Wv, Wo, pe);

    qkv_mma<<<dim3(DM / 128, NTOK / 128, 3), 256, SMEM_N128>>>(bq, bk, bv);

    transpose_v<<<dim3(SEQ / 32, HD / 32, NHB), 256>>>();

    qkcope<<<dim3(SEQ / 32, NHB), 256, FQ_SMEM>>>();

    av_mma<<<dim3(SEQ / 128, NHB), 256, SMEM_AV>>>();

    out_mma<<<dim3(DM / 128, NTOK / 128), 256, SMEM_N128>>>(bo, out);
}

// round 13
// speedup vs baseline: 1.2521x; 1.2521x over previous
#include <cuda_runtime.h>
#include <cuda_fp16.h>
#include <math.h>
#include <stdint.h>

#define SEQ   1024
#define BATCH 4
#define DM    1024
#define NH    16
#define HD    64
#define NPOS  1000
#define NTOK  (SEQ*BATCH)   // 4096
#define NHB   (NH*BATCH)    // 64

// ---------------------------------------------------------------------------
// Device scratch (no runtime allocation allowed) — all fp16
// ---------------------------------------------------------------------------
__device__ __align__(16) __half gx[NTOK*DM];
__device__ __align__(16) __half gw[4*DM*DM];          // WqT,WkT,WvT,WoT [n][k]
__device__ __align__(16) __half gpet[SEQ*HD];         // peT [n pad][d]
__device__ __align__(16) __half gq[NHB*SEQ*HD];
__device__ __align__(16) __half gk[NHB*SEQ*HD];
__device__ __align__(16) __half gv[NHB*SEQ*HD];
__device__ __align__(16) __half gvt[NHB*HD*SEQ];      // vT [hb][d][t]
__device__ __align__(16) __half g_logits[(size_t)NHB*SEQ*SEQ];  // 134 MB
__device__ __align__(16) __half g_li[(size_t)NHB*SEQ*SEQ];      // 134 MB
__device__ __align__(16) __half gp[(size_t)NHB*SEQ*SEQ];        // probs
__device__ __align__(16) __half gctx[NTOK*DM];

// ---------------------------------------------------------------------------
// Helpers (baseline PTX only)
// ---------------------------------------------------------------------------
__device__ __forceinline__ uint32_t smem_u32(const void* p) {
    uint32_t a;
    asm("{ .reg .u64 t; cvta.to.shared.u64 t, %1; cvt.u32.u64 %0, t; }"
        : "=r"(a) : "l"(p));
    return a;
}
__device__ __forceinline__ void ldm4(uint32_t* r, uint32_t addr) {
    asm volatile("ldmatrix.sync.aligned.m8n8.x4.shared.b16 {%0,%1,%2,%3}, [%4];"
        : "=r"(r[0]), "=r"(r[1]), "=r"(r[2]), "=r"(r[3]) : "r"(addr));
}
__device__ __forceinline__ void mma_f16(float* c, const uint32_t* a,
                                        const uint32_t* b) {
    asm volatile(
        "mma.sync.aligned.m16n8k16.row.col.f32.f16.f16.f32 "
        "{%0,%1,%2,%3}, {%4,%5,%6,%7}, {%8,%9}, {%0,%1,%2,%3};"
        : "+f"(c[0]), "+f"(c[1]), "+f"(c[2]), "+f"(c[3])
        : "r"(a[0]), "r"(a[1]), "r"(a[2]), "r"(a[3]), "r"(b[0]), "r"(b[1]));
}
__device__ __forceinline__ void cp16(uint32_t dst, const void* src) {
    asm volatile("cp.async.ca.shared.global [%0], [%1], 16;"
                 :: "r"(dst), "l"(src));
}
#define CP_COMMIT asm volatile("cp.async.commit_group;" ::: "memory")
template<int N>
__device__ __forceinline__ void cp_wait() {
    asm volatile("cp.async.wait_group %0;" :: "n"(N) : "memory");
}

__device__ __forceinline__ float sigmoidf_(float x) {
    return 1.0f / (1.0f + __expf(-x));
}

// ---------------------------------------------------------------------------
// Stage ROWSx32 fp16 K-major subtile via cp.async; pitch 80B.
// ---------------------------------------------------------------------------
template<int ROWS>
__device__ __forceinline__ void stage_cp(const __half* __restrict__ src, int ld,
                                         uint32_t smem_byte, int tid)
{
    #pragma unroll
    for (int it = 0; it < ROWS / 64; it++) {
        int q = tid + it * 256;
        int row = q >> 2, ch = q & 3;
        cp16(smem_byte + row * 80 + ch * 16, src + (size_t)row * ld + ch * 8);
    }
}

// ---------------------------------------------------------------------------
// Core: C[128 x NTILE*16] += A[128 x ktot] · B[NTILE*16 x ktot]^T
// fp16 single-product, fp32 accum. 64-k chunks (two 32-k subtiles per stage),
// STAGES-deep cp.async ring, ONE sync per 64-k chunk. 8 warps as 4(m) x 2(n).
// ---------------------------------------------------------------------------
template<int NTILE, int STAGES>
__device__ __forceinline__ void mma_core(
    const __half* A, int a_ld, const __half* B, int b_ld,
    int ktot, float acc[2][NTILE][4], char* smem)
{
    const int tid = threadIdx.x;
    const int warp = tid >> 5, lane = tid & 31;
    const int wm = warp >> 1, wn = warp & 1;
    constexpr int NROWS = NTILE * 16;
    constexpr int TA32 = 128 * 80;
    constexpr int TB32 = NROWS * 80;
    constexpr int TA = 2 * TA32;
    constexpr int TB = 2 * TB32;
    constexpr int STAGE = TA + TB;
    const uint32_t sb = smem_u32(smem);
    const int nch = ktot / 64;

    #pragma unroll
    for (int s = 0; s < STAGES - 1; s++) {
        if (s < nch) {
            uint32_t nb = sb + s * STAGE;
            stage_cp<128>(A + s * 64, a_ld, nb, tid);
            stage_cp<128>(A + s * 64 + 32, a_ld, nb + TA32, tid);
            stage_cp<NROWS>(B + s * 64, b_ld, nb + TA, tid);
            stage_cp<NROWS>(B + s * 64 + 32, b_ld, nb + TA + TB32, tid);
        }
        CP_COMMIT;
    }

    for (int c = 0; c < nch; c++) {
        cp_wait<STAGES - 2>();
        __syncthreads();
        int pf = c + STAGES - 1;
        if (pf < nch) {
            uint32_t nb = sb + (pf % STAGES) * STAGE;
            stage_cp<128>(A + pf * 64, a_ld, nb, tid);
            stage_cp<128>(A + pf * 64 + 32, a_ld, nb + TA32, tid);
            stage_cp<NROWS>(B + pf * 64, b_ld, nb + TA, tid);
            stage_cp<NROWS>(B + pf * 64 + 32, b_ld, nb + TA + TB32, tid);
        }
        CP_COMMIT;

        const uint32_t cb = sb + (c % STAGES) * STAGE;
        #pragma unroll
        for (int sub = 0; sub < 2; sub++) {
            const uint32_t ca = cb + sub * TA32;
            const uint32_t cbB = cb + TA + sub * TB32;
            #pragma unroll
            for (int kk = 0; kk < 32; kk += 16) {
                uint32_t ah[2][4];
                #pragma unroll
                for (int tm = 0; tm < 2; tm++) {
                    int r = wm * 32 + tm * 16 + ((lane >> 3) & 1) * 8 + (lane & 7);
                    int cc = kk + ((lane >> 4) & 1) * 8;
                    ldm4(ah[tm], ca + (uint32_t)(r * 80 + cc * 2));
                }
                #pragma unroll
                for (int p = 0; p < NTILE / 2; p++) {
                    uint32_t bh[4];
                    int r = wn * NTILE * 8 + p * 16 + ((lane >> 4) & 1) * 8 + (lane & 7);
                    int cc = kk + ((lane >> 3) & 1) * 8;
                    ldm4(bh, cbB + (uint32_t)(r * 80 + cc * 2));
                    #pragma unroll
                    for (int tm = 0; tm < 2; tm++) {
                        mma_f16(acc[tm][2 * p],     ah[tm], bh);
                        mma_f16(acc[tm][2 * p + 1], ah[tm], bh + 2);
                    }
                }
            }
        }
    }
}

#define SMEM_N128 (2 * (2 * 128 * 80 + 2 * 128 * 80))   // 81920 (2-stage, N128)
#define SMEM_AV   (3 * (2 * 128 * 80 + 2 * 64 * 80))    // 92160 (3-stage, N64)

// ---------------------------------------------------------------------------
// Prologue: z=0..3 W transposes; z=4 pe transpose (y<2); z=5 convert_x
// ---------------------------------------------------------------------------
__global__ __launch_bounds__(256) void prologue_conv(
    const float* __restrict__ Wq, const float* __restrict__ Wk,
    const float* __restrict__ Wv, const float* __restrict__ Wo,
    const float* __restrict__ pe, const float* __restrict__ x)
{
    __shared__ float t[32][33];
    int tx = threadIdx.x & 31, ty = threadIdx.x >> 5;
    int bx = blockIdx.x * 32, by = blockIdx.y * 32;
    int z = blockIdx.z;

    if (z < 4) {
        const float* W = (z == 0) ? Wq : (z == 1) ? Wk : (z == 2) ? Wv : Wo;
        size_t base = (size_t)z * DM * DM;
        #pragma unroll
        for (int j = 0; j < 4; j++)
            t[ty + 8 * j][tx] = W[(size_t)(by + ty + 8 * j) * DM + bx + tx];
        __syncthreads();
        #pragma unroll
        for (int j = 0; j < 4; j++)
            gw[base + (size_t)(bx + ty + 8 * j) * DM + by + tx] =
                __float2half_rn(t[tx][ty + 8 * j]);
    } else if (z == 4) {
        if (by >= HD) return;
        #pragma unroll
        for (int j = 0; j < 4; j++) {
            int d = by + ty + 8 * j, n = bx + tx;
            t[ty + 8 * j][tx] = (n < NPOS) ? pe[(size_t)d * NPOS + n] : 0.0f;
        }
        __syncthreads();
        #pragma unroll
        for (int j = 0; j < 4; j++)
            gpet[(size_t)(bx + ty + 8 * j) * HD + by + tx] =
                __float2half_rn(t[tx][ty + 8 * j]);
    } else {
        // convert_x: 1024 xy-blocks, each handles 4096 contiguous elements
        int blk = blockIdx.y * 32 + blockIdx.x;
        size_t i0 = (size_t)blk * 4096 + threadIdx.x * 4;
        #pragma unroll
        for (int it = 0; it < 4; it++) {
            size_t i = i0 + it * 1024;
            float4 v = *(const float4*)(x + i);
            *(__half2*)(gx + i)     = __floats2half2_rn(v.x, v.y);
            *(__half2*)(gx + i + 2) = __floats2half2_rn(v.z, v.w);
        }
    }
}

// ---------------------------------------------------------------------------
// K1: QKV projections (scatter to head layout, +bias) -> fp16 q,k,v
// ---------------------------------------------------------------------------
__global__ __launch_bounds__(256, 2) void qkv_mma(
    const float* __restrict__ bq, const float* __restrict__ bk,
    const float* __restrict__ bv)
{
    extern __shared__ char smem[];
    const int tid = threadIdx.x;
    const int warp = tid >> 5, lane = tid & 31;
    const int wm = warp >> 1, wn = warp & 1;
    const int n0b = blockIdx.x * 128, m0b = blockIdx.y * 128, z = blockIdx.z;
    const float* bias = (z == 0) ? bq : (z == 1) ? bk : bv;
    __half* out = (z == 0) ? gq : (z == 1) ? gk : gv;

    float acc[2][8][4] = {};
    mma_core<8, 2>(gx + (size_t)m0b * DM, DM,
                   gw + (size_t)z * DM * DM + (size_t)n0b * DM, DM,
                   DM, acc, smem);

    #pragma unroll
    for (int tm = 0; tm < 2; tm++) {
        #pragma unroll
        for (int tn = 0; tn < 8; tn++) {
            int c = n0b + wn * 64 + tn * 8 + 2 * (lane & 3);
            int h = c >> 6, d = c & 63;
            float2 bb = *(const float2*)(bias + c);
            #pragma unroll
            for (int half_ = 0; half_ < 2; half_++) {
                int m = m0b + wm * 32 + tm * 16 + (lane >> 2) + half_ * 8;
                int s = m >> 2, b_ = m & 3;
                __half2 v = __floats2half2_rn(acc[tm][tn][2 * half_ + 0] + bb.x,
                                              acc[tm][tn][2 * half_ + 1] + bb.y);
                *(__half2*)(out + ((size_t)(h * BATCH + b_) * SEQ + s) * HD + d) = v;
            }
        }
    }
}

// ---------------------------------------------------------------------------
// K2: merged logits/li GEMM per (h,b) PLUS transpose_v CTAs (z >= 128).
// z < 128: (z>>1)=hb, (z&1) selects K (logits) vs PE (li). K=64, one chunk.
// z >= 128: transpose gv -> gvt for hb = z - 128, tile = y*8+x (32 t x 2 d).
// ---------------------------------------------------------------------------
__global__ __launch_bounds__(256, 2) void qkqpe_mma()
{
    extern __shared__ char smem[];
    const int tid = threadIdx.x;

    if (blockIdx.z >= 2 * NHB) {
        // ---- transpose_v role ----
        __half (*t)[40] = (__half(*)[40])smem;
        int hb = blockIdx.z - 2 * NHB;
        int tile = blockIdx.y * 8 + blockIdx.x;      // 0..63
        int bx = (tile & 31) * 32;                    // t-dim
        int by = (tile >> 5) * 32;                    // d-dim
        const __half* V = gv + (size_t)hb * SEQ * HD;
        size_t base = (size_t)hb * HD * SEQ;
        int tx = tid & 31, ty = tid >> 5;
        #pragma unroll
        for (int j = 0; j < 4; j++)
            t[ty + 8 * j][tx] = V[(size_t)(bx + ty + 8 * j) * HD + by + tx];
        __syncthreads();
        #pragma unroll
        for (int j = 0; j < 4; j++)
            gvt[base + (size_t)(by + ty + 8 * j) * SEQ + bx + tx] = t[tx][ty + 8 * j];
        return;
    }

    const int warp = tid >> 5, lane = tid & 31;
    const int wm = warp >> 1, wn = warp & 1;
    const int t0b = blockIdx.x * 128, m0b = blockIdx.y * 128;
    const int hb = blockIdx.z >> 1, which = blockIdx.z & 1;

    const __half* A = gq + (size_t)hb * SEQ * HD + (size_t)m0b * HD;
    const __half* B = which ? gpet + (size_t)t0b * HD
                            : gk + (size_t)hb * SEQ * HD + (size_t)t0b * HD;
    __half* Lb = (which ? g_li : g_logits) + ((size_t)hb << 20);
    const float scale = which ? 1.0f : 0.125f;

    float acc[2][8][4] = {};
    mma_core<8, 2>(A, HD, B, HD, HD, acc, smem);

    #pragma unroll
    for (int tm = 0; tm < 2; tm++) {
        #pragma unroll
        for (int tn = 0; tn < 8; tn++) {
            int c = t0b + wn * 64 + tn * 8 + 2 * (lane & 3);
            #pragma unroll
            for (int half_ = 0; half_ < 2; half_++) {
                int m = m0b + wm * 32 + tm * 16 + (lane >> 2) + half_ * 8;
                __half2 v = __floats2half2_rn(acc[tm][tn][2 * half_ + 0] * scale,
                                              acc[tm][tn][2 * half_ + 1] * scale);
                *(__half2*)(Lb + (size_t)m * SEQ + c) = v;
            }
        }
    }
}

// ---------------------------------------------------------------------------
// K4: per-row CoPE + softmax; fp16 in / fp16 probs out, fp32 math inside.
// ---------------------------------------------------------------------------
__global__ __launch_bounds__(128) void cope_softmax()
{
    __shared__ __align__(16) float s_li[SEQ];
    __shared__ float s_w[4];
    __shared__ float s_m[4];
    __shared__ float s_s[4];

    const size_t row = blockIdx.x;
    __half* L = g_logits + (row << 10);
    const __half* li = g_li + (row << 10);
    const int tid = threadIdx.x;
    const int lane = tid & 31, warp = tid >> 5;

    {
        uint4 u = *(const uint4*)(li + tid * 8);
        const __half2* hp = (const __half2*)&u;
        #pragma unroll
        for (int i = 0; i < 4; i++) {
            float2 f = __half22float2(hp[i]);
            s_li[tid * 8 + 2 * i + 0] = f.x;
            s_li[tid * 8 + 2 * i + 1] = f.y;
        }
    }

    float l[8];
    {
        uint4 u = *(const uint4*)(L + tid * 8);
        const __half2* hp = (const __half2*)&u;
        #pragma unroll
        for (int i = 0; i < 4; i++) {
            float2 f = __half22float2(hp[i]);
            l[2 * i + 0] = f.x;
            l[2 * i + 1] = f.y;
        }
    }

    float su[8];
    {
        float g = sigmoidf_(l[7]); su[7] = g;
        #pragma unroll
        for (int j = 6; j >= 0; j--) su[j] = su[j + 1] + sigmoidf_(l[j]);
    }
    float total = su[0];

    float v = total;
    #pragma unroll
    for (int off = 1; off < 32; off <<= 1) {
        float n = __shfl_down_sync(0xffffffffu, v, off);
        if (lane + off < 32) v += n;
    }
    if (lane == 0) s_w[warp] = v;
    __syncthreads();

    float basew = 0.f;
    #pragma unroll
    for (int w = 0; w < 4; w++) if (w > warp) basew += s_w[w];
    float base = basew + (v - total);

    #pragma unroll
    for (int j = 0; j < 8; j++) {
        float p = fminf(base + su[j], 999.0f);
        float pf = floorf(p);
        float w = p - pf;
        int fi = (int)pf;
        int ci = (int)ceilf(p);
        l[j] += s_li[ci] * w + s_li[fi] * (1.0f - w);
    }

    float m = l[0];
    #pragma unroll
    for (int j = 1; j < 8; j++) m = fmaxf(m, l[j]);
    #pragma unroll
    for (int off = 16; off; off >>= 1)
        m = fmaxf(m, __shfl_xor_sync(0xffffffffu, m, off));
    if (lane == 0) s_m[warp] = m;
    __syncthreads();
    m = fmaxf(fmaxf(s_m[0], s_m[1]), fmaxf(s_m[2], s_m[3]));

    float sum = 0.f;
    #pragma unroll
    for (int j = 0; j < 8; j++) { l[j] = __expf(l[j] - m); sum += l[j]; }
    #pragma unroll
    for (int off = 16; off; off >>= 1)
        sum += __shfl_xor_sync(0xffffffffu, sum, off);
    if (lane == 0) s_s[warp] = sum;
    __syncthreads();
    float inv = 1.0f / (s_s[0] + s_s[1] + s_s[2] + s_s[3]);

    union { __half2 h2[4]; uint4 u; } pv;
    #pragma unroll
    for (int i = 0; i < 4; i++)
        pv.h2[i] = __floats2half2_rn(l[2 * i] * inv, l[2 * i + 1] * inv);
    *(uint4*)(gp + (row << 10) + tid * 8) = pv.u;
}

// ---------------------------------------------------------------------------
// K5: ctx = attn · V per (h,b). N = 64 -> fp16 ctx (3-stage, 64-k chunks)
// ---------------------------------------------------------------------------
__global__ __launch_bounds__(256, 2) void av_mma()
{
    extern __shared__ char smem[];
    const int tid = threadIdx.x;
    const int warp = tid >> 5, lane = tid & 31;
    const int wm = warp >> 1, wn = warp & 1;
    const int m0b = blockIdx.x * 128, hb = blockIdx.y;
    const int h = hb >> 2, b_ = hb & 3;

    float acc[2][4][4] = {};
    mma_core<4, 3>(gp + ((size_t)hb << 20) + (size_t)m0b * SEQ, SEQ,
                   gvt + (size_t)hb * HD * SEQ, SEQ,
                   SEQ, acc, smem);

    #pragma unroll
    for (int tm = 0; tm < 2; tm++) {
        #pragma unroll
        for (int tn = 0; tn < 4; tn++) {
            int d = wn * 32 + tn * 8 + 2 * (lane & 3);
            #pragma unroll
            for (int half_ = 0; half_ < 2; half_++) {
                int s = m0b + wm * 32 + tm * 16 + (lane >> 2) + half_ * 8;
                __half2 v = __floats2half2_rn(acc[tm][tn][2 * half_ + 0],
                                              acc[tm][tn][2 * half_ + 1]);
                *(__half2*)(gctx + ((size_t)s * BATCH + b_) * DM + h * HD + d) = v;
            }
        }
    }
}

// ---------------------------------------------------------------------------
// K6: output projection (+bias) -> fp32 out
// ---------------------------------------------------------------------------
__global__ __launch_bounds__(256, 2) void out_mma(const float* __restrict__ bo,
                                                  float* __restrict__ out)
{
    extern __shared__ char smem[];
    const int tid = threadIdx.x;
    const int warp = tid >> 5, lane = tid & 31;
    const int wm = warp >> 1, wn = warp & 1;
    const int n0b = blockIdx.x * 128, m0b = blockIdx.y * 128;

    float acc[2][8][4] = {};
    mma_core<8, 2>(gctx + (size_t)m0b * DM, DM,
                   gw + (size_t)3 * DM * DM + (size_t)n0b * DM, DM,
                   DM, acc, smem);

    #pragma unroll
    for (int tm = 0; tm < 2; tm++) {
        #pragma unroll
        for (int tn = 0; tn < 8; tn++) {
            int c = n0b + wn * 64 + tn * 8 + 2 * (lane & 3);
            float2 bb = *(const float2*)(bo + c);
            #pragma unroll
            for (int half_ = 0; half_ < 2; half_++) {
                int m = m0b + wm * 32 + tm * 16 + (lane >> 2) + half_ * 8;
                float2 v;
                v.x = acc[tm][tn][2 * half_ + 0] + bb.x;
                v.y = acc[tm][tn][2 * half_ + 1] + bb.y;
                *(float2*)(out + (size_t)m * DM + c) = v;
            }
        }
    }
}

// ---------------------------------------------------------------------------
extern "C" void kernel_launch(void* const* d_in, const int* in_sizes, int n_in,
                              void* d_out, int out_size)
{
    const float* x  = (const float*)d_in[0];
    const float* Wq = (const float*)d_in[1];
    const float* bq = (const float*)d_in[2];
    const float* Wk = (const float*)d_in[3];
    const float* bk = (const float*)d_in[4];
    const float* Wv = (const float*)d_in[5];
    const float* bv = (const float*)d_in[6];
    const float* Wo = (const float*)d_in[7];
    const float* bo = (const float*)d_in[8];
    const float* pe = (const float*)d_in[9];
    float* out = (float*)d_out;

    cudaFuncSetAttribute(qkv_mma,   cudaFuncAttributeMaxDynamicSharedMemorySize, SMEM_N128);
    cudaFuncSetAttribute(out_mma,   cudaFuncAttributeMaxDynamicSharedMemorySize, SMEM_N128);
    cudaFuncSetAttribute(qkqpe_mma, cudaFuncAttributeMaxDynamicSharedMemorySize, SMEM_N128);
    cudaFuncSetAttribute(av_mma,    cudaFuncAttributeMaxDynamicSharedMemorySize, SMEM_AV);

    prologue_conv<<<dim3(DM / 32, DM / 32, 6), 256>>>(Wq, Wk, Wv, Wo, pe, x);

    qkv_mma<<<dim3(DM / 128, NTOK / 128, 3), 256, SMEM_N128>>>(bq, bk, bv);

    // z < 128: QK / QPE GEMMs; z >= 128: transpose_v (overlapped)
    qkqpe_mma<<<dim3(SEQ / 128, SEQ / 128, 2 * NHB + NHB), 256, SMEM_N128>>>();

    cope_softmax<<<NHB * SEQ, 128>>>();

    av_mma<<<dim3(SEQ / 128, NHB), 256, SMEM_AV>>>();

    out_mma<<<dim3(DM / 128, NTOK / 128), 256, SMEM_N128>>>(bo, out);
}

// round 14
// speedup vs baseline: 1.3316x; 1.0635x over previous
#include <cuda_runtime.h>
#include <cuda_fp16.h>
#include <math.h>
#include <stdint.h>

#define SEQ   1024
#define BATCH 4
#define DM    1024
#define NH    16
#define HD    64
#define NPOS  1000
#define NTOK  (SEQ*BATCH)   // 4096
#define NHB   (NH*BATCH)    // 64

// ---------------------------------------------------------------------------
// Device scratch (no runtime allocation allowed) — all fp16
// ---------------------------------------------------------------------------
__device__ __align__(16) __half gx[NTOK*DM];
__device__ __align__(16) __half gw[4*DM*DM];          // WqT,WkT,WvT,WoT [n][k]
__device__ __align__(16) __half gpet[SEQ*HD];         // peT [n pad][d]
__device__ __align__(16) __half gq[NHB*SEQ*HD];
__device__ __align__(16) __half gk[NHB*SEQ*HD];
__device__ __align__(16) __half gv[NHB*SEQ*HD];
__device__ __align__(16) __half gvt[NHB*HD*SEQ];      // vT [hb][d][t]
__device__ __align__(16) __half g_logits[(size_t)NHB*SEQ*SEQ];  // 134 MB
__device__ __align__(16) __half g_li[(size_t)NHB*SEQ*SEQ];      // 134 MB
__device__ __align__(16) __half gp[(size_t)NHB*SEQ*SEQ];        // probs
__device__ __align__(16) __half gctx[NTOK*DM];

// ---------------------------------------------------------------------------
// Helpers (baseline PTX only)
// ---------------------------------------------------------------------------
__device__ __forceinline__ uint32_t smem_u32(const void* p) {
    uint32_t a;
    asm("{ .reg .u64 t; cvta.to.shared.u64 t, %1; cvt.u32.u64 %0, t; }"
        : "=r"(a) : "l"(p));
    return a;
}
__device__ __forceinline__ void ldm4(uint32_t* r, uint32_t addr) {
    asm volatile("ldmatrix.sync.aligned.m8n8.x4.shared.b16 {%0,%1,%2,%3}, [%4];"
        : "=r"(r[0]), "=r"(r[1]), "=r"(r[2]), "=r"(r[3]) : "r"(addr));
}
__device__ __forceinline__ void mma_f16(float* c, const uint32_t* a,
                                        const uint32_t* b) {
    asm volatile(
        "mma.sync.aligned.m16n8k16.row.col.f32.f16.f16.f32 "
        "{%0,%1,%2,%3}, {%4,%5,%6,%7}, {%8,%9}, {%0,%1,%2,%3};"
        : "+f"(c[0]), "+f"(c[1]), "+f"(c[2]), "+f"(c[3])
        : "r"(a[0]), "r"(a[1]), "r"(a[2]), "r"(a[3]), "r"(b[0]), "r"(b[1]));
}
__device__ __forceinline__ void cp16(uint32_t dst, const void* src) {
    asm volatile("cp.async.ca.shared.global [%0], [%1], 16;"
                 :: "r"(dst), "l"(src));
}
#define CP_COMMIT asm volatile("cp.async.commit_group;" ::: "memory")
template<int N>
__device__ __forceinline__ void cp_wait() {
    asm volatile("cp.async.wait_group %0;" :: "n"(N) : "memory");
}

__device__ __forceinline__ float ex2_(float x) {
    float r;
    asm("ex2.approx.f32 %0, %1;" : "=f"(r) : "f"(x));
    return r;
}
__device__ __forceinline__ float sigmoidf_(float x) {
    return __fdividef(1.0f, 1.0f + __expf(-x));
}

// ---------------------------------------------------------------------------
// Stage ROWSx32 fp16 K-major subtile via cp.async; pitch 80B.
// ---------------------------------------------------------------------------
template<int ROWS>
__device__ __forceinline__ void stage_cp(const __half* __restrict__ src, int ld,
                                         uint32_t smem_byte, int tid)
{
    #pragma unroll
    for (int it = 0; it < ROWS / 64; it++) {
        int q = tid + it * 256;
        int row = q >> 2, ch = q & 3;
        cp16(smem_byte + row * 80 + ch * 16, src + (size_t)row * ld + ch * 8);
    }
}

// ---------------------------------------------------------------------------
// Core: C[128 x NTILE*16] += A[128 x ktot] · B[NTILE*16 x ktot]^T
// fp16 single-product, fp32 accum. 64-k chunks (two 32-k subtiles per stage),
// STAGES-deep cp.async ring, ONE sync per 64-k chunk. 8 warps as 4(m) x 2(n).
// ---------------------------------------------------------------------------
template<int NTILE, int STAGES>
__device__ __forceinline__ void mma_core(
    const __half* A, int a_ld, const __half* B, int b_ld,
    int ktot, float acc[2][NTILE][4], char* smem)
{
    const int tid = threadIdx.x;
    const int warp = tid >> 5, lane = tid & 31;
    const int wm = warp >> 1, wn = warp & 1;
    constexpr int NROWS = NTILE * 16;
    constexpr int TA32 = 128 * 80;
    constexpr int TB32 = NROWS * 80;
    constexpr int TA = 2 * TA32;
    constexpr int TB = 2 * TB32;
    constexpr int STAGE = TA + TB;
    const uint32_t sb = smem_u32(smem);
    const int nch = ktot / 64;

    #pragma unroll
    for (int s = 0; s < STAGES - 1; s++) {
        if (s < nch) {
            uint32_t nb = sb + s * STAGE;
            stage_cp<128>(A + s * 64, a_ld, nb, tid);
            stage_cp<128>(A + s * 64 + 32, a_ld, nb + TA32, tid);
            stage_cp<NROWS>(B + s * 64, b_ld, nb + TA, tid);
            stage_cp<NROWS>(B + s * 64 + 32, b_ld, nb + TA + TB32, tid);
        }
        CP_COMMIT;
    }

    for (int c = 0; c < nch; c++) {
        cp_wait<STAGES - 2>();
        __syncthreads();
        int pf = c + STAGES - 1;
        if (pf < nch) {
            uint32_t nb = sb + (pf % STAGES) * STAGE;
            stage_cp<128>(A + pf * 64, a_ld, nb, tid);
            stage_cp<128>(A + pf * 64 + 32, a_ld, nb + TA32, tid);
            stage_cp<NROWS>(B + pf * 64, b_ld, nb + TA, tid);
            stage_cp<NROWS>(B + pf * 64 + 32, b_ld, nb + TA + TB32, tid);
        }
        CP_COMMIT;

        const uint32_t cb = sb + (c % STAGES) * STAGE;
        #pragma unroll
        for (int sub = 0; sub < 2; sub++) {
            const uint32_t ca = cb + sub * TA32;
            const uint32_t cbB = cb + TA + sub * TB32;
            #pragma unroll
            for (int kk = 0; kk < 32; kk += 16) {
                uint32_t ah[2][4];
                #pragma unroll
                for (int tm = 0; tm < 2; tm++) {
                    int r = wm * 32 + tm * 16 + ((lane >> 3) & 1) * 8 + (lane & 7);
                    int cc = kk + ((lane >> 4) & 1) * 8;
                    ldm4(ah[tm], ca + (uint32_t)(r * 80 + cc * 2));
                }
                #pragma unroll
                for (int p = 0; p < NTILE / 2; p++) {
                    uint32_t bh[4];
                    int r = wn * NTILE * 8 + p * 16 + ((lane >> 4) & 1) * 8 + (lane & 7);
                    int cc = kk + ((lane >> 3) & 1) * 8;
                    ldm4(bh, cbB + (uint32_t)(r * 80 + cc * 2));
                    #pragma unroll
                    for (int tm = 0; tm < 2; tm++) {
                        mma_f16(acc[tm][2 * p],     ah[tm], bh);
                        mma_f16(acc[tm][2 * p + 1], ah[tm], bh + 2);
                    }
                }
            }
        }
    }
}

#define SMEM_N128 (2 * (2 * 128 * 80 + 2 * 128 * 80))   // 81920 (2-stage, N128)
#define SMEM_AV   (3 * (2 * 128 * 80 + 2 * 64 * 80))    // 92160 (3-stage, N64)

// ---------------------------------------------------------------------------
// Prologue conversion kernels
// ---------------------------------------------------------------------------
__global__ __launch_bounds__(256) void convert_x(const float* __restrict__ x)
{
    int i = (blockIdx.x * 256 + threadIdx.x) * 4;
    float4 v = *(const float4*)(x + i);
    *(__half2*)(gx + i)     = __floats2half2_rn(v.x, v.y);
    *(__half2*)(gx + i + 2) = __floats2half2_rn(v.z, v.w);
}

// z = 0..3: W transposes; z = 4: pe transpose (y < 2 active)
__global__ __launch_bounds__(256) void transpose_wpe(
    const float* __restrict__ Wq, const float* __restrict__ Wk,
    const float* __restrict__ Wv, const float* __restrict__ Wo,
    const float* __restrict__ pe)
{
    __shared__ float t[32][33];
    int tx = threadIdx.x & 31, ty = threadIdx.x >> 5;
    int bx = blockIdx.x * 32, by = blockIdx.y * 32;
    int z = blockIdx.z;

    if (z < 4) {
        const float* W = (z == 0) ? Wq : (z == 1) ? Wk : (z == 2) ? Wv : Wo;
        size_t base = (size_t)z * DM * DM;
        #pragma unroll
        for (int j = 0; j < 4; j++)
            t[ty + 8 * j][tx] = W[(size_t)(by + ty + 8 * j) * DM + bx + tx];
        __syncthreads();
        #pragma unroll
        for (int j = 0; j < 4; j++)
            gw[base + (size_t)(bx + ty + 8 * j) * DM + by + tx] =
                __float2half_rn(t[tx][ty + 8 * j]);
    } else {
        if (by >= HD) return;
        #pragma unroll
        for (int j = 0; j < 4; j++) {
            int d = by + ty + 8 * j, n = bx + tx;
            t[ty + 8 * j][tx] = (n < NPOS) ? pe[(size_t)d * NPOS + n] : 0.0f;
        }
        __syncthreads();
        #pragma unroll
        for (int j = 0; j < 4; j++)
            gpet[(size_t)(bx + ty + 8 * j) * HD + by + tx] =
                __float2half_rn(t[tx][ty + 8 * j]);
    }
}

__global__ __launch_bounds__(256) void transpose_v()
{
    __shared__ __half t[32][40];
    int hb = blockIdx.z;
    const __half* V = gv + (size_t)hb * SEQ * HD;
    size_t base = (size_t)hb * HD * SEQ;
    int tx = threadIdx.x & 31, ty = threadIdx.x >> 5;
    int bx = blockIdx.x * 32, by = blockIdx.y * 32;   // bx: t, by: d
    #pragma unroll
    for (int j = 0; j < 4; j++)
        t[ty + 8 * j][tx] = V[(size_t)(bx + ty + 8 * j) * HD + by + tx];
    __syncthreads();
    #pragma unroll
    for (int j = 0; j < 4; j++)
        gvt[base + (size_t)(by + ty + 8 * j) * SEQ + bx + tx] = t[tx][ty + 8 * j];
}

// ---------------------------------------------------------------------------
// K1: QKV projections (scatter to head layout, +bias) -> fp16 q,k,v
// ---------------------------------------------------------------------------
__global__ __launch_bounds__(256, 2) void qkv_mma(
    const float* __restrict__ bq, const float* __restrict__ bk,
    const float* __restrict__ bv)
{
    extern __shared__ char smem[];
    const int tid = threadIdx.x;
    const int warp = tid >> 5, lane = tid & 31;
    const int wm = warp >> 1, wn = warp & 1;
    const int n0b = blockIdx.x * 128, m0b = blockIdx.y * 128, z = blockIdx.z;
    const float* bias = (z == 0) ? bq : (z == 1) ? bk : bv;
    __half* out = (z == 0) ? gq : (z == 1) ? gk : gv;

    float acc[2][8][4] = {};
    mma_core<8, 2>(gx + (size_t)m0b * DM, DM,
                   gw + (size_t)z * DM * DM + (size_t)n0b * DM, DM,
                   DM, acc, smem);

    #pragma unroll
    for (int tm = 0; tm < 2; tm++) {
        #pragma unroll
        for (int tn = 0; tn < 8; tn++) {
            int c = n0b + wn * 64 + tn * 8 + 2 * (lane & 3);
            int h = c >> 6, d = c & 63;
            float2 bb = *(const float2*)(bias + c);
            #pragma unroll
            for (int half_ = 0; half_ < 2; half_++) {
                int m = m0b + wm * 32 + tm * 16 + (lane >> 2) + half_ * 8;
                int s = m >> 2, b_ = m & 3;
                __half2 v = __floats2half2_rn(acc[tm][tn][2 * half_ + 0] + bb.x,
                                              acc[tm][tn][2 * half_ + 1] + bb.y);
                *(__half2*)(out + ((size_t)(h * BATCH + b_) * SEQ + s) * HD + d) = v;
            }
        }
    }
}

// ---------------------------------------------------------------------------
// K2: merged logits/li GEMM per (h,b). z&1 selects K (logits) vs PE (li).
// K=64 -> single 64-k chunk, one barrier.
// ---------------------------------------------------------------------------
__global__ __launch_bounds__(256, 2) void qkqpe_mma()
{
    extern __shared__ char smem[];
    const int tid = threadIdx.x;
    const int warp = tid >> 5, lane = tid & 31;
    const int wm = warp >> 1, wn = warp & 1;
    const int t0b = blockIdx.x * 128, m0b = blockIdx.y * 128;
    const int hb = blockIdx.z >> 1, which = blockIdx.z & 1;

    const __half* A = gq + (size_t)hb * SEQ * HD + (size_t)m0b * HD;
    const __half* B = which ? gpet + (size_t)t0b * HD
                            : gk + (size_t)hb * SEQ * HD + (size_t)t0b * HD;
    __half* Lb = (which ? g_li : g_logits) + ((size_t)hb << 20);
    const float scale = which ? 1.0f : 0.125f;

    float acc[2][8][4] = {};
    mma_core<8, 2>(A, HD, B, HD, HD, acc, smem);

    #pragma unroll
    for (int tm = 0; tm < 2; tm++) {
        #pragma unroll
        for (int tn = 0; tn < 8; tn++) {
            int c = t0b + wn * 64 + tn * 8 + 2 * (lane & 3);
            #pragma unroll
            for (int half_ = 0; half_ < 2; half_++) {
                int m = m0b + wm * 32 + tm * 16 + (lane >> 2) + half_ * 8;
                __half2 v = __floats2half2_rn(acc[tm][tn][2 * half_ + 0] * scale,
                                              acc[tm][tn][2 * half_ + 1] * scale);
                *(__half2*)(Lb + (size_t)m * SEQ + c) = v;
            }
        }
    }
}

// ---------------------------------------------------------------------------
// K4: per-row CoPE + softmax; instruction-dieted.
// li staged raw fp16; approx rcp; ci = fi+1; ex2-form softmax exp.
// ---------------------------------------------------------------------------
__global__ __launch_bounds__(128) void cope_softmax()
{
    __shared__ __align__(16) __half s_li[SEQ];
    __shared__ float s_w[4];
    __shared__ float s_m[4];
    __shared__ float s_s[4];

    const size_t row = blockIdx.x;
    __half* L = g_logits + (row << 10);
    const __half* li = g_li + (row << 10);
    const int tid = threadIdx.x;
    const int lane = tid & 31, warp = tid >> 5;

    // stage li row raw (fp16)
    *(uint4*)(s_li + tid * 8) = *(const uint4*)(li + tid * 8);

    float l[8];
    {
        uint4 u = *(const uint4*)(L + tid * 8);
        const __half2* hp = (const __half2*)&u;
        #pragma unroll
        for (int i = 0; i < 4; i++) {
            float2 f = __half22float2(hp[i]);
            l[2 * i + 0] = f.x;
            l[2 * i + 1] = f.y;
        }
    }

    float su[8];
    {
        float g = sigmoidf_(l[7]); su[7] = g;
        #pragma unroll
        for (int j = 6; j >= 0; j--) su[j] = su[j + 1] + sigmoidf_(l[j]);
    }
    float total = su[0];

    float v = total;
    #pragma unroll
    for (int off = 1; off < 32; off <<= 1) {
        float n = __shfl_down_sync(0xffffffffu, v, off);
        if (lane + off < 32) v += n;
    }
    if (lane == 0) s_w[warp] = v;
    __syncthreads();                 // also covers s_li staging

    float basew = 0.f;
    #pragma unroll
    for (int w = 0; w < 4; w++) if (w > warp) basew += s_w[w];
    float base = basew + (v - total);

    #pragma unroll
    for (int j = 0; j < 8; j++) {
        float p = fminf(base + su[j], 999.0f);
        float pf = floorf(p);
        float w = p - pf;
        int fi = (int)pf;
        float lf = __half2float(s_li[fi]);
        float lc = __half2float(s_li[fi + 1]);   // s_li[1000]=0 pad; w=0 there
        l[j] += lf + w * (lc - lf);
    }

    float m = l[0];
    #pragma unroll
    for (int j = 1; j < 8; j++) m = fmaxf(m, l[j]);
    #pragma unroll
    for (int off = 16; off; off >>= 1)
        m = fmaxf(m, __shfl_xor_sync(0xffffffffu, m, off));
    if (lane == 0) s_m[warp] = m;
    __syncthreads();
    m = fmaxf(fmaxf(s_m[0], s_m[1]), fmaxf(s_m[2], s_m[3]));

    const float L2E = 1.4426950408889634f;
    float nm = -m * L2E;
    float sum = 0.f;
    #pragma unroll
    for (int j = 0; j < 8; j++) {
        l[j] = ex2_(fmaf(l[j], L2E, nm));
        sum += l[j];
    }
    #pragma unroll
    for (int off = 16; off; off >>= 1)
        sum += __shfl_xor_sync(0xffffffffu, sum, off);
    if (lane == 0) s_s[warp] = sum;
    __syncthreads();
    float inv = __fdividef(1.0f, s_s[0] + s_s[1] + s_s[2] + s_s[3]);

    union { __half2 h2[4]; uint4 u; } pv;
    #pragma unroll
    for (int i = 0; i < 4; i++)
        pv.h2[i] = __floats2half2_rn(l[2 * i] * inv, l[2 * i + 1] * inv);
    *(uint4*)(gp + (row << 10) + tid * 8) = pv.u;
}

// ---------------------------------------------------------------------------
// K5: ctx = attn · V per (h,b). N = 64 -> fp16 ctx (3-stage, 64-k chunks)
// ---------------------------------------------------------------------------
__global__ __launch_bounds__(256, 2) void av_mma()
{
    extern __shared__ char smem[];
    const int tid = threadIdx.x;
    const int warp = tid >> 5, lane = tid & 31;
    const int wm = warp >> 1, wn = warp & 1;
    const int m0b = blockIdx.x * 128, hb = blockIdx.y;
    const int h = hb >> 2, b_ = hb & 3;

    float acc[2][4][4] = {};
    mma_core<4, 3>(gp + ((size_t)hb << 20) + (size_t)m0b * SEQ, SEQ,
                   gvt + (size_t)hb * HD * SEQ, SEQ,
                   SEQ, acc, smem);

    #pragma unroll
    for (int tm = 0; tm < 2; tm++) {
        #pragma unroll
        for (int tn = 0; tn < 4; tn++) {
            int d = wn * 32 + tn * 8 + 2 * (lane & 3);
            #pragma unroll
            for (int half_ = 0; half_ < 2; half_++) {
                int s = m0b + wm * 32 + tm * 16 + (lane >> 2) + half_ * 8;
                __half2 v = __floats2half2_rn(acc[tm][tn][2 * half_ + 0],
                                              acc[tm][tn][2 * half_ + 1]);
                *(__half2*)(gctx + ((size_t)s * BATCH + b_) * DM + h * HD + d) = v;
            }
        }
    }
}

// ---------------------------------------------------------------------------
// K6: output projection (+bias) -> fp32 out
// ---------------------------------------------------------------------------
__global__ __launch_bounds__(256, 2) void out_mma(const float* __restrict__ bo,
                                                  float* __restrict__ out)
{
    extern __shared__ char smem[];
    const int tid = threadIdx.x;
    const int warp = tid >> 5, lane = tid & 31;
    const int wm = warp >> 1, wn = warp & 1;
    const int n0b = blockIdx.x * 128, m0b = blockIdx.y * 128;

    float acc[2][8][4] = {};
    mma_core<8, 2>(gctx + (size_t)m0b * DM, DM,
                   gw + (size_t)3 * DM * DM + (size_t)n0b * DM, DM,
                   DM, acc, smem);

    #pragma unroll
    for (int tm = 0; tm < 2; tm++) {
        #pragma unroll
        for (int tn = 0; tn < 8; tn++) {
            int c = n0b + wn * 64 + tn * 8 + 2 * (lane & 3);
            float2 bb = *(const float2*)(bo + c);
            #pragma unroll
            for (int half_ = 0; half_ < 2; half_++) {
                int m = m0b + wm * 32 + tm * 16 + (lane >> 2) + half_ * 8;
                float2 v;
                v.x = acc[tm][tn][2 * half_ + 0] + bb.x;
                v.y = acc[tm][tn][2 * half_ + 1] + bb.y;
                *(float2*)(out + (size_t)m * DM + c) = v;
            }
        }
    }
}

// ---------------------------------------------------------------------------
extern "C" void kernel_launch(void* const* d_in, const int* in_sizes, int n_in,
                              void* d_out, int out_size)
{
    const float* x  = (const float*)d_in[0];
    const float* Wq = (const float*)d_in[1];
    const float* bq = (const float*)d_in[2];
    const float* Wk = (const float*)d_in[3];
    const float* bk = (const float*)d_in[4];
    const float* Wv = (const float*)d_in[5];
    const float* bv = (const float*)d_in[6];
    const float* Wo = (const float*)d_in[7];
    const float* bo = (const float*)d_in[8];
    const float* pe = (const float*)d_in[9];
    float* out = (float*)d_out;

    cudaFuncSetAttribute(qkv_mma,   cudaFuncAttributeMaxDynamicSharedMemorySize, SMEM_N128);
    cudaFuncSetAttribute(out_mma,   cudaFuncAttributeMaxDynamicSharedMemorySize, SMEM_N128);
    cudaFuncSetAttribute(qkqpe_mma, cudaFuncAttributeMaxDynamicSharedMemorySize, SMEM_N128);
    cudaFuncSetAttribute(av_mma,    cudaFuncAttributeMaxDynamicSharedMemorySize, SMEM_AV);

    convert_x<<<NTOK * DM / 1024, 256>>>(x);
    transpose_wpe<<<dim3(DM / 32, DM / 32, 5), 256>>>(Wq, Wk, Wv, Wo, pe);

    qkv_mma<<<dim3(DM / 128, NTOK / 128, 3), 256, SMEM_N128>>>(bq, bk, bv);

    transpose_v<<<dim3(SEQ / 32, HD / 32, NHB), 256>>>();

    qkqpe_mma<<<dim3(SEQ / 128, SEQ / 128, 2 * NHB), 256, SMEM_N128>>>();

    cope_softmax<<<NHB * SEQ, 128>>>();

    av_mma<<<dim3(SEQ / 128, NHB), 256, SMEM_AV>>>();

    out_mma<<<dim3(DM / 128, NTOK / 128), 256, SMEM_N128>>>(bo, out);
}

// round 15
// speedup vs baseline: 1.3431x; 1.0086x over previous
#include <cuda_runtime.h>
#include <cuda_fp16.h>
#include <math.h>
#include <stdint.h>

#define SEQ   1024
#define BATCH 4
#define DM    1024
#define NH    16
#define HD    64
#define NPOS  1000
#define NTOK  (SEQ*BATCH)   // 4096
#define NHB   (NH*BATCH)    // 64

// ---------------------------------------------------------------------------
// Device scratch (no runtime allocation allowed) — all fp16
// ---------------------------------------------------------------------------
__device__ __align__(16) __half gx[NTOK*DM];
__device__ __align__(16) __half gw[4*DM*DM];          // WqT,WkT,WvT,WoT [n][k]
__device__ __align__(16) __half gpet[SEQ*HD];         // peT [n pad][d]
__device__ __align__(16) __half gq[NHB*SEQ*HD];
__device__ __align__(16) __half gk[NHB*SEQ*HD];
__device__ __align__(16) __half gv[NHB*SEQ*HD];
__device__ __align__(16) __half gvt[NHB*HD*SEQ];      // vT [hb][d][t]
__device__ __align__(16) __half g_logits[(size_t)NHB*SEQ*SEQ];  // 134 MB
__device__ __align__(16) __half g_li[(size_t)NHB*SEQ*SEQ];      // 134 MB
__device__ __align__(16) __half gp[(size_t)NHB*SEQ*SEQ];        // probs
__device__ __align__(16) __half gctx[NTOK*DM];

// ---------------------------------------------------------------------------
// Helpers (baseline PTX only)
// ---------------------------------------------------------------------------
__device__ __forceinline__ uint32_t smem_u32(const void* p) {
    uint32_t a;
    asm("{ .reg .u64 t; cvta.to.shared.u64 t, %1; cvt.u32.u64 %0, t; }"
        : "=r"(a) : "l"(p));
    return a;
}
__device__ __forceinline__ void ldm4(uint32_t* r, uint32_t addr) {
    asm volatile("ldmatrix.sync.aligned.m8n8.x4.shared.b16 {%0,%1,%2,%3}, [%4];"
        : "=r"(r[0]), "=r"(r[1]), "=r"(r[2]), "=r"(r[3]) : "r"(addr));
}
__device__ __forceinline__ void mma_f16(float* c, const uint32_t* a,
                                        const uint32_t* b) {
    asm volatile(
        "mma.sync.aligned.m16n8k16.row.col.f32.f16.f16.f32 "
        "{%0,%1,%2,%3}, {%4,%5,%6,%7}, {%8,%9}, {%0,%1,%2,%3};"
        : "+f"(c[0]), "+f"(c[1]), "+f"(c[2]), "+f"(c[3])
        : "r"(a[0]), "r"(a[1]), "r"(a[2]), "r"(a[3]), "r"(b[0]), "r"(b[1]));
}
__device__ __forceinline__ void cp16(uint32_t dst, const void* src) {
    asm volatile("cp.async.ca.shared.global [%0], [%1], 16;"
                 :: "r"(dst), "l"(src));
}
#define CP_COMMIT asm volatile("cp.async.commit_group;" ::: "memory")
template<int N>
__device__ __forceinline__ void cp_wait() {
    asm volatile("cp.async.wait_group %0;" :: "n"(N) : "memory");
}
// streaming (evict-first) 32-bit store / 128-bit load
__device__ __forceinline__ void stcs32(void* p, uint32_t v) {
    asm volatile("st.global.cs.b32 [%0], %1;" :: "l"(p), "r"(v) : "memory");
}
__device__ __forceinline__ uint4 ldcs128(const void* p) {
    uint4 r;
    asm volatile("ld.global.cs.v4.b32 {%0,%1,%2,%3}, [%4];"
        : "=r"(r.x), "=r"(r.y), "=r"(r.z), "=r"(r.w) : "l"(p));
    return r;
}

__device__ __forceinline__ float ex2_(float x) {
    float r;
    asm("ex2.approx.f32 %0, %1;" : "=f"(r) : "f"(x));
    return r;
}
__device__ __forceinline__ float sigmoidf_(float x) {
    return __fdividef(1.0f, 1.0f + __expf(-x));
}

// ---------------------------------------------------------------------------
// Stage ROWSx32 fp16 K-major subtile via cp.async; pitch 80B.
// ---------------------------------------------------------------------------
template<int ROWS>
__device__ __forceinline__ void stage_cp(const __half* __restrict__ src, int ld,
                                         uint32_t smem_byte, int tid)
{
    #pragma unroll
    for (int it = 0; it < ROWS / 64; it++) {
        int q = tid + it * 256;
        int row = q >> 2, ch = q & 3;
        cp16(smem_byte + row * 80 + ch * 16, src + (size_t)row * ld + ch * 8);
    }
}

// ---------------------------------------------------------------------------
// Core: C[128 x NTILE*16] += A[128 x ktot] · B[NTILE*16 x ktot]^T
// fp16 single-product, fp32 accum. 64-k chunks (two 32-k subtiles per stage),
// STAGES-deep cp.async ring, ONE sync per 64-k chunk. 8 warps as 4(m) x 2(n).
// ---------------------------------------------------------------------------
template<int NTILE, int STAGES>
__device__ __forceinline__ void mma_core(
    const __half* A, int a_ld, const __half* B, int b_ld,
    int ktot, float acc[2][NTILE][4], char* smem)
{
    const int tid = threadIdx.x;
    const int warp = tid >> 5, lane = tid & 31;
    const int wm = warp >> 1, wn = warp & 1;
    constexpr int NROWS = NTILE * 16;
    constexpr int TA32 = 128 * 80;
    constexpr int TB32 = NROWS * 80;
    constexpr int TA = 2 * TA32;
    constexpr int TB = 2 * TB32;
    constexpr int STAGE = TA + TB;
    const uint32_t sb = smem_u32(smem);
    const int nch = ktot / 64;

    #pragma unroll
    for (int s = 0; s < STAGES - 1; s++) {
        if (s < nch) {
            uint32_t nb = sb + s * STAGE;
            stage_cp<128>(A + s * 64, a_ld, nb, tid);
            stage_cp<128>(A + s * 64 + 32, a_ld, nb + TA32, tid);
            stage_cp<NROWS>(B + s * 64, b_ld, nb + TA, tid);
            stage_cp<NROWS>(B + s * 64 + 32, b_ld, nb + TA + TB32, tid);
        }
        CP_COMMIT;
    }

    for (int c = 0; c < nch; c++) {
        cp_wait<STAGES - 2>();
        __syncthreads();
        int pf = c + STAGES - 1;
        if (pf < nch) {
            uint32_t nb = sb + (pf % STAGES) * STAGE;
            stage_cp<128>(A + pf * 64, a_ld, nb, tid);
            stage_cp<128>(A + pf * 64 + 32, a_ld, nb + TA32, tid);
            stage_cp<NROWS>(B + pf * 64, b_ld, nb + TA, tid);
            stage_cp<NROWS>(B + pf * 64 + 32, b_ld, nb + TA + TB32, tid);
        }
        CP_COMMIT;

        const uint32_t cb = sb + (c % STAGES) * STAGE;
        #pragma unroll
        for (int sub = 0; sub < 2; sub++) {
            const uint32_t ca = cb + sub * TA32;
            const uint32_t cbB = cb + TA + sub * TB32;
            #pragma unroll
            for (int kk = 0; kk < 32; kk += 16) {
                uint32_t ah[2][4];
                #pragma unroll
                for (int tm = 0; tm < 2; tm++) {
                    int r = wm * 32 + tm * 16 + ((lane >> 3) & 1) * 8 + (lane & 7);
                    int cc = kk + ((lane >> 4) & 1) * 8;
                    ldm4(ah[tm], ca + (uint32_t)(r * 80 + cc * 2));
                }
                #pragma unroll
                for (int p = 0; p < NTILE / 2; p++) {
                    uint32_t bh[4];
                    int r = wn * NTILE * 8 + p * 16 + ((lane >> 4) & 1) * 8 + (lane & 7);
                    int cc = kk + ((lane >> 3) & 1) * 8;
                    ldm4(bh, cbB + (uint32_t)(r * 80 + cc * 2));
                    #pragma unroll
                    for (int tm = 0; tm < 2; tm++) {
                        mma_f16(acc[tm][2 * p],     ah[tm], bh);
                        mma_f16(acc[tm][2 * p + 1], ah[tm], bh + 2);
                    }
                }
            }
        }
    }
}

#define SMEM_N128 (2 * (2 * 128 * 80 + 2 * 128 * 80))   // 81920 (2-stage, N128)
#define SMEM_AV   (3 * (2 * 128 * 80 + 2 * 64 * 80))    // 92160 (3-stage, N64)

// ---------------------------------------------------------------------------
// Prologue: z=0..3 W transposes; z=4 pe transpose (y<2); z=5 convert_x
// ---------------------------------------------------------------------------
__global__ __launch_bounds__(256) void prologue_conv(
    const float* __restrict__ Wq, const float* __restrict__ Wk,
    const float* __restrict__ Wv, const float* __restrict__ Wo,
    const float* __restrict__ pe, const float* __restrict__ x)
{
    __shared__ float t[32][33];
    int tx = threadIdx.x & 31, ty = threadIdx.x >> 5;
    int bx = blockIdx.x * 32, by = blockIdx.y * 32;
    int z = blockIdx.z;

    if (z < 4) {
        const float* W = (z == 0) ? Wq : (z == 1) ? Wk : (z == 2) ? Wv : Wo;
        size_t base = (size_t)z * DM * DM;
        #pragma unroll
        for (int j = 0; j < 4; j++)
            t[ty + 8 * j][tx] = W[(size_t)(by + ty + 8 * j) * DM + bx + tx];
        __syncthreads();
        #pragma unroll
        for (int j = 0; j < 4; j++)
            gw[base + (size_t)(bx + ty + 8 * j) * DM + by + tx] =
                __float2half_rn(t[tx][ty + 8 * j]);
    } else if (z == 4) {
        if (by >= HD) return;
        #pragma unroll
        for (int j = 0; j < 4; j++) {
            int d = by + ty + 8 * j, n = bx + tx;
            t[ty + 8 * j][tx] = (n < NPOS) ? pe[(size_t)d * NPOS + n] : 0.0f;
        }
        __syncthreads();
        #pragma unroll
        for (int j = 0; j < 4; j++)
            gpet[(size_t)(bx + ty + 8 * j) * HD + by + tx] =
                __float2half_rn(t[tx][ty + 8 * j]);
    } else {
        // convert_x: 1024 xy-blocks, each handles 4096 contiguous elements
        int blk = blockIdx.y * 32 + blockIdx.x;
        size_t i0 = (size_t)blk * 4096 + threadIdx.x * 4;
        #pragma unroll
        for (int it = 0; it < 4; it++) {
            size_t i = i0 + it * 1024;
            float4 v = *(const float4*)(x + i);
            *(__half2*)(gx + i)     = __floats2half2_rn(v.x, v.y);
            *(__half2*)(gx + i + 2) = __floats2half2_rn(v.z, v.w);
        }
    }
}

__global__ __launch_bounds__(256) void transpose_v()
{
    __shared__ __half t[32][40];
    int hb = blockIdx.z;
    const __half* V = gv + (size_t)hb * SEQ * HD;
    size_t base = (size_t)hb * HD * SEQ;
    int tx = threadIdx.x & 31, ty = threadIdx.x >> 5;
    int bx = blockIdx.x * 32, by = blockIdx.y * 32;   // bx: t, by: d
    #pragma unroll
    for (int j = 0; j < 4; j++)
        t[ty + 8 * j][tx] = V[(size_t)(bx + ty + 8 * j) * HD + by + tx];
    __syncthreads();
    #pragma unroll
    for (int j = 0; j < 4; j++)
        gvt[base + (size_t)(by + ty + 8 * j) * SEQ + bx + tx] = t[tx][ty + 8 * j];
}

// ---------------------------------------------------------------------------
// K1: QKV projections (scatter to head layout, +bias) -> fp16 q,k,v
// ---------------------------------------------------------------------------
__global__ __launch_bounds__(256, 2) void qkv_mma(
    const float* __restrict__ bq, const float* __restrict__ bk,
    const float* __restrict__ bv)
{
    extern __shared__ char smem[];
    const int tid = threadIdx.x;
    const int warp = tid >> 5, lane = tid & 31;
    const int wm = warp >> 1, wn = warp & 1;
    const int n0b = blockIdx.x * 128, m0b = blockIdx.y * 128, z = blockIdx.z;
    const float* bias = (z == 0) ? bq : (z == 1) ? bk : bv;
    __half* out = (z == 0) ? gq : (z == 1) ? gk : gv;

    float acc[2][8][4] = {};
    mma_core<8, 2>(gx + (size_t)m0b * DM, DM,
                   gw + (size_t)z * DM * DM + (size_t)n0b * DM, DM,
                   DM, acc, smem);

    #pragma unroll
    for (int tm = 0; tm < 2; tm++) {
        #pragma unroll
        for (int tn = 0; tn < 8; tn++) {
            int c = n0b + wn * 64 + tn * 8 + 2 * (lane & 3);
            int h = c >> 6, d = c & 63;
            float2 bb = *(const float2*)(bias + c);
            #pragma unroll
            for (int half_ = 0; half_ < 2; half_++) {
                int m = m0b + wm * 32 + tm * 16 + (lane >> 2) + half_ * 8;
                int s = m >> 2, b_ = m & 3;
                __half2 v = __floats2half2_rn(acc[tm][tn][2 * half_ + 0] + bb.x,
                                              acc[tm][tn][2 * half_ + 1] + bb.y);
                *(__half2*)(out + ((size_t)(h * BATCH + b_) * SEQ + s) * HD + d) = v;
            }
        }
    }
}

// ---------------------------------------------------------------------------
// K2: merged logits/li GEMM per (h,b). z&1 selects K (logits) vs PE (li).
// K=64 -> single 64-k chunk. Streaming stores (write-once, read-once data).
// ---------------------------------------------------------------------------
__global__ __launch_bounds__(256, 2) void qkqpe_mma()
{
    extern __shared__ char smem[];
    const int tid = threadIdx.x;
    const int warp = tid >> 5, lane = tid & 31;
    const int wm = warp >> 1, wn = warp & 1;
    const int t0b = blockIdx.x * 128, m0b = blockIdx.y * 128;
    const int hb = blockIdx.z >> 1, which = blockIdx.z & 1;

    const __half* A = gq + (size_t)hb * SEQ * HD + (size_t)m0b * HD;
    const __half* B = which ? gpet + (size_t)t0b * HD
                            : gk + (size_t)hb * SEQ * HD + (size_t)t0b * HD;
    __half* Lb = (which ? g_li : g_logits) + ((size_t)hb << 20);
    const float scale = which ? 1.0f : 0.125f;

    float acc[2][8][4] = {};
    mma_core<8, 2>(A, HD, B, HD, HD, acc, smem);

    #pragma unroll
    for (int tm = 0; tm < 2; tm++) {
        #pragma unroll
        for (int tn = 0; tn < 8; tn++) {
            int c = t0b + wn * 64 + tn * 8 + 2 * (lane & 3);
            #pragma unroll
            for (int half_ = 0; half_ < 2; half_++) {
                int m = m0b + wm * 32 + tm * 16 + (lane >> 2) + half_ * 8;
                __half2 v = __floats2half2_rn(acc[tm][tn][2 * half_ + 0] * scale,
                                              acc[tm][tn][2 * half_ + 1] * scale);
                stcs32(Lb + (size_t)m * SEQ + c, *(uint32_t*)&v);
            }
        }
    }
}

// ---------------------------------------------------------------------------
// K4: per-row CoPE + softmax; streaming loads; instruction-dieted.
// ---------------------------------------------------------------------------
__global__ __launch_bounds__(128) void cope_softmax()
{
    __shared__ __align__(16) __half s_li[SEQ];
    __shared__ float s_w[4];
    __shared__ float s_m[4];
    __shared__ float s_s[4];

    const size_t row = blockIdx.x;
    __half* L = g_logits + (row << 10);
    const __half* li = g_li + (row << 10);
    const int tid = threadIdx.x;
    const int lane = tid & 31, warp = tid >> 5;

    // stage li row raw (fp16, streaming)
    *(uint4*)(s_li + tid * 8) = ldcs128(li + tid * 8);

    float l[8];
    {
        uint4 u = ldcs128(L + tid * 8);
        const __half2* hp = (const __half2*)&u;
        #pragma unroll
        for (int i = 0; i < 4; i++) {
            float2 f = __half22float2(hp[i]);
            l[2 * i + 0] = f.x;
            l[2 * i + 1] = f.y;
        }
    }

    float su[8];
    {
        float g = sigmoidf_(l[7]); su[7] = g;
        #pragma unroll
        for (int j = 6; j >= 0; j--) su[j] = su[j + 1] + sigmoidf_(l[j]);
    }
    float total = su[0];

    float v = total;
    #pragma unroll
    for (int off = 1; off < 32; off <<= 1) {
        float n = __shfl_down_sync(0xffffffffu, v, off);
        if (lane + off < 32) v += n;
    }
    if (lane == 0) s_w[warp] = v;
    __syncthreads();                 // also covers s_li staging

    float basew = 0.f;
    #pragma unroll
    for (int w = 0; w < 4; w++) if (w > warp) basew += s_w[w];
    float base = basew + (v - total);

    float m = -INFINITY;
    #pragma unroll
    for (int j = 0; j < 8; j++) {
        float p = fminf(base + su[j], 999.0f);
        float pf = floorf(p);
        float w = p - pf;
        int fi = (int)pf;
        float lf = __half2float(s_li[fi]);
        float lc = __half2float(s_li[fi + 1]);   // s_li[1000]=0 pad; w=0 there
        l[j] += lf + w * (lc - lf);
        m = fmaxf(m, l[j]);
    }

    #pragma unroll
    for (int off = 16; off; off >>= 1)
        m = fmaxf(m, __shfl_xor_sync(0xffffffffu, m, off));
    if (lane == 0) s_m[warp] = m;
    __syncthreads();
    m = fmaxf(fmaxf(s_m[0], s_m[1]), fmaxf(s_m[2], s_m[3]));

    const float L2E = 1.4426950408889634f;
    float nm = -m * L2E;
    float sum = 0.f;
    #pragma unroll
    for (int j = 0; j < 8; j++) {
        l[j] = ex2_(fmaf(l[j], L2E, nm));
        sum += l[j];
    }
    #pragma unroll
    for (int off = 16; off; off >>= 1)
        sum += __shfl_xor_sync(0xffffffffu, sum, off);
    if (lane == 0) s_s[warp] = sum;
    __syncthreads();
    float inv = __fdividef(1.0f, s_s[0] + s_s[1] + s_s[2] + s_s[3]);

    union { __half2 h2[4]; uint4 u; } pv;
    #pragma unroll
    for (int i = 0; i < 4; i++)
        pv.h2[i] = __floats2half2_rn(l[2 * i] * inv, l[2 * i + 1] * inv);
    *(uint4*)(gp + (row << 10) + tid * 8) = pv.u;
}

// ---------------------------------------------------------------------------
// K5: ctx = attn · V per (h,b). N = 64 -> fp16 ctx (3-stage, 64-k chunks)
// ---------------------------------------------------------------------------
__global__ __launch_bounds__(256, 2) void av_mma()
{
    extern __shared__ char smem[];
    const int tid = threadIdx.x;
    const int warp = tid >> 5, lane = tid & 31;
    const int wm = warp >> 1, wn = warp & 1;
    const int m0b = blockIdx.x * 128, hb = blockIdx.y;
    const int h = hb >> 2, b_ = hb & 3;

    float acc[2][4][4] = {};
    mma_core<4, 3>(gp + ((size_t)hb << 20) + (size_t)m0b * SEQ, SEQ,
                   gvt + (size_t)hb * HD * SEQ, SEQ,
                   SEQ, acc, smem);

    #pragma unroll
    for (int tm = 0; tm < 2; tm++) {
        #pragma unroll
        for (int tn = 0; tn < 4; tn++) {
            int d = wn * 32 + tn * 8 + 2 * (lane & 3);
            #pragma unroll
            for (int half_ = 0; half_ < 2; half_++) {
                int s = m0b + wm * 32 + tm * 16 + (lane >> 2) + half_ * 8;
                __half2 v = __floats2half2_rn(acc[tm][tn][2 * half_ + 0],
                                              acc[tm][tn][2 * half_ + 1]);
                *(__half2*)(gctx + ((size_t)s * BATCH + b_) * DM + h * HD + d) = v;
            }
        }
    }
}

// ---------------------------------------------------------------------------
// K6: output projection (+bias) -> fp32 out
// ---------------------------------------------------------------------------
__global__ __launch_bounds__(256, 2) void out_mma(const float* __restrict__ bo,
                                                  float* __restrict__ out)
{
    extern __shared__ char smem[];
    const int tid = threadIdx.x;
    const int warp = tid >> 5, lane = tid & 31;
    const int wm = warp >> 1, wn = warp & 1;
    const int n0b = blockIdx.x * 128, m0b = blockIdx.y * 128;

    float acc[2][8][4] = {};
    mma_core<8, 2>(gctx + (size_t)m0b * DM, DM,
                   gw + (size_t)3 * DM * DM + (size_t)n0b * DM, DM,
                   DM, acc, smem);

    #pragma unroll
    for (int tm = 0; tm < 2; tm++) {
        #pragma unroll
        for (int tn = 0; tn < 8; tn++) {
            int c = n0b + wn * 64 + tn * 8 + 2 * (lane & 3);
            float2 bb = *(const float2*)(bo + c);
            #pragma unroll
            for (int half_ = 0; half_ < 2; half_++) {
                int m = m0b + wm * 32 + tm * 16 + (lane >> 2) + half_ * 8;
                float2 v;
                v.x = acc[tm][tn][2 * half_ + 0] + bb.x;
                v.y = acc[tm][tn][2 * half_ + 1] + bb.y;
                *(float2*)(out + (size_t)m * DM + c) = v;
            }
        }
    }
}

// ---------------------------------------------------------------------------
extern "C" void kernel_launch(void* const* d_in, const int* in_sizes, int n_in,
                              void* d_out, int out_size)
{
    const float* x  = (const float*)d_in[0];
    const float* Wq = (const float*)d_in[1];
    const float* bq = (const float*)d_in[2];
    const float* Wk = (const float*)d_in[3];
    const float* bk = (const float*)d_in[4];
    const float* Wv = (const float*)d_in[5];
    const float* bv = (const float*)d_in[6];
    const float* Wo = (const float*)d_in[7];
    const float* bo = (const float*)d_in[8];
    const float* pe = (const float*)d_in[9];
    float* out = (float*)d_out;

    cudaFuncSetAttribute(qkv_mma,   cudaFuncAttributeMaxDynamicSharedMemorySize, SMEM_N128);
    cudaFuncSetAttribute(out_mma,   cudaFuncAttributeMaxDynamicSharedMemorySize, SMEM_N128);
    cudaFuncSetAttribute(qkqpe_mma, cudaFuncAttributeMaxDynamicSharedMemorySize, SMEM_N128);
    cudaFuncSetAttribute(av_mma,    cudaFuncAttributeMaxDynamicSharedMemorySize, SMEM_AV);

    prologue_conv<<<dim3(DM / 32, DM / 32, 6), 256>>>(Wq, Wk, Wv, Wo, pe, x);

    qkv_mma<<<dim3(DM / 128, NTOK / 128, 3), 256, SMEM_N128>>>(bq, bk, bv);

    transpose_v<<<dim3(SEQ / 32, HD / 32, NHB), 256>>>();

    qkqpe_mma<<<dim3(SEQ / 128, SEQ / 128, 2 * NHB), 256, SMEM_N128>>>();

    cope_softmax<<<NHB * SEQ, 128>>>();

    av_mma<<<dim3(SEQ / 128, NHB), 256, SMEM_AV>>>();

    out_mma<<<dim3(DM / 128, NTOK / 128), 256, SMEM_N128>>>(bo, out);
}

// round 16
// speedup vs baseline: 1.3850x; 1.0312x over previous
#include <cuda_runtime.h>
#include <cuda_fp16.h>
#include <math.h>
#include <stdint.h>

#define SEQ   1024
#define BATCH 4
#define DM    1024
#define NH    16
#define HD    64
#define NPOS  1000
#define NTOK  (SEQ*BATCH)   // 4096
#define NHB   (NH*BATCH)    // 64

// ---------------------------------------------------------------------------
// Device scratch (no runtime allocation allowed) — all fp16
// ---------------------------------------------------------------------------
__device__ __align__(16) __half gx[NTOK*DM];
__device__ __align__(16) __half gw[4*DM*DM];          // WqT,WkT,WvT,WoT [n][k]
__device__ __align__(16) __half gpet[SEQ*HD];         // peT [n pad][d]
__device__ __align__(16) __half gq[NHB*SEQ*HD];
__device__ __align__(16) __half gk[NHB*SEQ*HD];
__device__ __align__(16) __half gv[NHB*SEQ*HD];
__device__ __align__(16) __half gvt[NHB*HD*SEQ];      // vT [hb][d][t]
__device__ __align__(16) __half g_logits[(size_t)NHB*SEQ*SEQ];  // 134 MB
__device__ __align__(16) __half g_li[(size_t)NHB*SEQ*SEQ];      // 134 MB
__device__ __align__(16) __half gp[(size_t)NHB*SEQ*SEQ];        // probs
__device__ __align__(16) __half gctx[NTOK*DM];

// ---------------------------------------------------------------------------
// Helpers (baseline PTX only)
// ---------------------------------------------------------------------------
__device__ __forceinline__ uint32_t smem_u32(const void* p) {
    uint32_t a;
    asm("{ .reg .u64 t; cvta.to.shared.u64 t, %1; cvt.u32.u64 %0, t; }"
        : "=r"(a) : "l"(p));
    return a;
}
__device__ __forceinline__ void ldm4(uint32_t* r, uint32_t addr) {
    asm volatile("ldmatrix.sync.aligned.m8n8.x4.shared.b16 {%0,%1,%2,%3}, [%4];"
        : "=r"(r[0]), "=r"(r[1]), "=r"(r[2]), "=r"(r[3]) : "r"(addr));
}
__device__ __forceinline__ void mma_f16(float* c, const uint32_t* a,
                                        const uint32_t* b) {
    asm volatile(
        "mma.sync.aligned.m16n8k16.row.col.f32.f16.f16.f32 "
        "{%0,%1,%2,%3}, {%4,%5,%6,%7}, {%8,%9}, {%0,%1,%2,%3};"
        : "+f"(c[0]), "+f"(c[1]), "+f"(c[2]), "+f"(c[3])
        : "r"(a[0]), "r"(a[1]), "r"(a[2]), "r"(a[3]), "r"(b[0]), "r"(b[1]));
}
__device__ __forceinline__ void cp16(uint32_t dst, const void* src) {
    asm volatile("cp.async.ca.shared.global [%0], [%1], 16;"
                 :: "r"(dst), "l"(src));
}
#define CP_COMMIT asm volatile("cp.async.commit_group;" ::: "memory")
template<int N>
__device__ __forceinline__ void cp_wait() {
    asm volatile("cp.async.wait_group %0;" :: "n"(N) : "memory");
}
// streaming (evict-first) 32-bit store / 128-bit load
__device__ __forceinline__ void stcs32(void* p, uint32_t v) {
    asm volatile("st.global.cs.b32 [%0], %1;" :: "l"(p), "r"(v) : "memory");
}
__device__ __forceinline__ uint4 ldcs128(const void* p) {
    uint4 r;
    asm volatile("ld.global.cs.v4.b32 {%0,%1,%2,%3}, [%4];"
        : "=r"(r.x), "=r"(r.y), "=r"(r.z), "=r"(r.w) : "l"(p));
    return r;
}

__device__ __forceinline__ float ex2_(float x) {
    float r;
    asm("ex2.approx.f32 %0, %1;" : "=f"(r) : "f"(x));
    return r;
}
__device__ __forceinline__ float sigmoidf_(float x) {
    return __fdividef(1.0f, 1.0f + __expf(-x));
}

// ---------------------------------------------------------------------------
// Stage ROWSx32 fp16 K-major subtile via cp.async; pitch 80B.
// ---------------------------------------------------------------------------
template<int ROWS>
__device__ __forceinline__ void stage_cp(const __half* __restrict__ src, int ld,
                                         uint32_t smem_byte, int tid)
{
    #pragma unroll
    for (int it = 0; it < ROWS / 64; it++) {
        int q = tid + it * 256;
        int row = q >> 2, ch = q & 3;
        cp16(smem_byte + row * 80 + ch * 16, src + (size_t)row * ld + ch * 8);
    }
}

// ---------------------------------------------------------------------------
// Core: C[128 x NTILE*16] += A[128 x ktot] · B[NTILE*16 x ktot]^T
// fp16 single-product, fp32 accum. 64-k chunks (two 32-k subtiles per stage),
// STAGES-deep cp.async ring, ONE sync per 64-k chunk. 8 warps as 4(m) x 2(n).
// ---------------------------------------------------------------------------
template<int NTILE, int STAGES>
__device__ __forceinline__ void mma_core(
    const __half* A, int a_ld, const __half* B, int b_ld,
    int ktot, float acc[2][NTILE][4], char* smem)
{
    const int tid = threadIdx.x;
    const int warp = tid >> 5, lane = tid & 31;
    const int wm = warp >> 1, wn = warp & 1;
    constexpr int NROWS = NTILE * 16;
    constexpr int TA32 = 128 * 80;
    constexpr int TB32 = NROWS * 80;
    constexpr int TA = 2 * TA32;
    constexpr int TB = 2 * TB32;
    constexpr int STAGE = TA + TB;
    const uint32_t sb = smem_u32(smem);
    const int nch = ktot / 64;

    #pragma unroll
    for (int s = 0; s < STAGES - 1; s++) {
        if (s < nch) {
            uint32_t nb = sb + s * STAGE;
            stage_cp<128>(A + s * 64, a_ld, nb, tid);
            stage_cp<128>(A + s * 64 + 32, a_ld, nb + TA32, tid);
            stage_cp<NROWS>(B + s * 64, b_ld, nb + TA, tid);
            stage_cp<NROWS>(B + s * 64 + 32, b_ld, nb + TA + TB32, tid);
        }
        CP_COMMIT;
    }

    for (int c = 0; c < nch; c++) {
        cp_wait<STAGES - 2>();
        __syncthreads();
        int pf = c + STAGES - 1;
        if (pf < nch) {
            uint32_t nb = sb + (pf % STAGES) * STAGE;
            stage_cp<128>(A + pf * 64, a_ld, nb, tid);
            stage_cp<128>(A + pf * 64 + 32, a_ld, nb + TA32, tid);
            stage_cp<NROWS>(B + pf * 64, b_ld, nb + TA, tid);
            stage_cp<NROWS>(B + pf * 64 + 32, b_ld, nb + TA + TB32, tid);
        }
        CP_COMMIT;

        const uint32_t cb = sb + (c % STAGES) * STAGE;
        #pragma unroll
        for (int sub = 0; sub < 2; sub++) {
            const uint32_t ca = cb + sub * TA32;
            const uint32_t cbB = cb + TA + sub * TB32;
            #pragma unroll
            for (int kk = 0; kk < 32; kk += 16) {
                uint32_t ah[2][4];
                #pragma unroll
                for (int tm = 0; tm < 2; tm++) {
                    int r = wm * 32 + tm * 16 + ((lane >> 3) & 1) * 8 + (lane & 7);
                    int cc = kk + ((lane >> 4) & 1) * 8;
                    ldm4(ah[tm], ca + (uint32_t)(r * 80 + cc * 2));
                }
                #pragma unroll
                for (int p = 0; p < NTILE / 2; p++) {
                    uint32_t bh[4];
                    int r = wn * NTILE * 8 + p * 16 + ((lane >> 4) & 1) * 8 + (lane & 7);
                    int cc = kk + ((lane >> 3) & 1) * 8;
                    ldm4(bh, cbB + (uint32_t)(r * 80 + cc * 2));
                    #pragma unroll
                    for (int tm = 0; tm < 2; tm++) {
                        mma_f16(acc[tm][2 * p],     ah[tm], bh);
                        mma_f16(acc[tm][2 * p + 1], ah[tm], bh + 2);
                    }
                }
            }
        }
    }
}

#define SMEM_N128 (2 * (2 * 128 * 80 + 2 * 128 * 80))   // 81920 (2-stage, N128)
#define SMEM_AV   (3 * (2 * 128 * 80 + 2 * 64 * 80))    // 92160 (3-stage, N64)
#define SMEM_QKPE (6 * 128 * 80)                        // 61440 (Q + Bk + Bpe)

// ---------------------------------------------------------------------------
// Prologue: z=0..3 W transposes; z=4 pe transpose (y<2); z=5 convert_x
// ---------------------------------------------------------------------------
__global__ __launch_bounds__(256) void prologue_conv(
    const float* __restrict__ Wq, const float* __restrict__ Wk,
    const float* __restrict__ Wv, const float* __restrict__ Wo,
    const float* __restrict__ pe, const float* __restrict__ x)
{
    __shared__ float t[32][33];
    int tx = threadIdx.x & 31, ty = threadIdx.x >> 5;
    int bx = blockIdx.x * 32, by = blockIdx.y * 32;
    int z = blockIdx.z;

    if (z < 4) {
        const float* W = (z == 0) ? Wq : (z == 1) ? Wk : (z == 2) ? Wv : Wo;
        size_t base = (size_t)z * DM * DM;
        #pragma unroll
        for (int j = 0; j < 4; j++)
            t[ty + 8 * j][tx] = W[(size_t)(by + ty + 8 * j) * DM + bx + tx];
        __syncthreads();
        #pragma unroll
        for (int j = 0; j < 4; j++)
            gw[base + (size_t)(bx + ty + 8 * j) * DM + by + tx] =
                __float2half_rn(t[tx][ty + 8 * j]);
    } else if (z == 4) {
        if (by >= HD) return;
        #pragma unroll
        for (int j = 0; j < 4; j++) {
            int d = by + ty + 8 * j, n = bx + tx;
            t[ty + 8 * j][tx] = (n < NPOS) ? pe[(size_t)d * NPOS + n] : 0.0f;
        }
        __syncthreads();
        #pragma unroll
        for (int j = 0; j < 4; j++)
            gpet[(size_t)(bx + ty + 8 * j) * HD + by + tx] =
                __float2half_rn(t[tx][ty + 8 * j]);
    } else {
        int blk = blockIdx.y * 32 + blockIdx.x;
        size_t i0 = (size_t)blk * 4096 + threadIdx.x * 4;
        #pragma unroll
        for (int it = 0; it < 4; it++) {
            size_t i = i0 + it * 1024;
            float4 v = *(const float4*)(x + i);
            *(__half2*)(gx + i)     = __floats2half2_rn(v.x, v.y);
            *(__half2*)(gx + i + 2) = __floats2half2_rn(v.z, v.w);
        }
    }
}

__global__ __launch_bounds__(256) void transpose_v()
{
    __shared__ __half t[32][40];
    int hb = blockIdx.z;
    const __half* V = gv + (size_t)hb * SEQ * HD;
    size_t base = (size_t)hb * HD * SEQ;
    int tx = threadIdx.x & 31, ty = threadIdx.x >> 5;
    int bx = blockIdx.x * 32, by = blockIdx.y * 32;   // bx: t, by: d
    #pragma unroll
    for (int j = 0; j < 4; j++)
        t[ty + 8 * j][tx] = V[(size_t)(bx + ty + 8 * j) * HD + by + tx];
    __syncthreads();
    #pragma unroll
    for (int j = 0; j < 4; j++)
        gvt[base + (size_t)(by + ty + 8 * j) * SEQ + bx + tx] = t[tx][ty + 8 * j];
}

// ---------------------------------------------------------------------------
// K1: QKV projections (scatter to head layout, +bias) -> fp16 q,k,v
// ---------------------------------------------------------------------------
__global__ __launch_bounds__(256, 2) void qkv_mma(
    const float* __restrict__ bq, const float* __restrict__ bk,
    const float* __restrict__ bv)
{
    extern __shared__ char smem[];
    const int tid = threadIdx.x;
    const int warp = tid >> 5, lane = tid & 31;
    const int wm = warp >> 1, wn = warp & 1;
    const int n0b = blockIdx.x * 128, m0b = blockIdx.y * 128, z = blockIdx.z;
    const float* bias = (z == 0) ? bq : (z == 1) ? bk : bv;
    __half* out = (z == 0) ? gq : (z == 1) ? gk : gv;

    float acc[2][8][4] = {};
    mma_core<8, 2>(gx + (size_t)m0b * DM, DM,
                   gw + (size_t)z * DM * DM + (size_t)n0b * DM, DM,
                   DM, acc, smem);

    #pragma unroll
    for (int tm = 0; tm < 2; tm++) {
        #pragma unroll
        for (int tn = 0; tn < 8; tn++) {
            int c = n0b + wn * 64 + tn * 8 + 2 * (lane & 3);
            int h = c >> 6, d = c & 63;
            float2 bb = *(const float2*)(bias + c);
            #pragma unroll
            for (int half_ = 0; half_ < 2; half_++) {
                int m = m0b + wm * 32 + tm * 16 + (lane >> 2) + half_ * 8;
                int s = m >> 2, b_ = m & 3;
                __half2 v = __floats2half2_rn(acc[tm][tn][2 * half_ + 0] + bb.x,
                                              acc[tm][tn][2 * half_ + 1] + bb.y);
                *(__half2*)(out + ((size_t)(h * BATCH + b_) * SEQ + s) * HD + d) = v;
            }
        }
    }
}

// ---------------------------------------------------------------------------
// K2 (merged): one CTA per (hb, m-tile, t-tile) computes BOTH
// logits = 0.125*Q·K^T and li = Q·PE^T. Q staged+fragmented once;
// Bpe load and logits store overlap phase-1 MMA. Streaming stores.
// smem: Q [0,20480) ; Bk [20480,40960) ; Bpe [40960,61440)
// ---------------------------------------------------------------------------
__global__ __launch_bounds__(256, 2) void qkqpe_mma()
{
    extern __shared__ char smem[];
    const int tid = threadIdx.x;
    const int warp = tid >> 5, lane = tid & 31;
    const int wm = warp >> 1, wn = warp & 1;
    const int t0b = blockIdx.x * 128, m0b = blockIdx.y * 128, hb = blockIdx.z;
    const uint32_t sb = smem_u32(smem);

    const __half* Q  = gq + (size_t)hb * SEQ * HD + (size_t)m0b * HD;
    const __half* K  = gk + (size_t)hb * SEQ * HD + (size_t)t0b * HD;
    const __half* PE = gpet + (size_t)t0b * HD;

    stage_cp<128>(Q, HD, sb, tid);
    stage_cp<128>(Q + 32, HD, sb + 10240, tid);
    stage_cp<128>(K, HD, sb + 20480, tid);
    stage_cp<128>(K + 32, HD, sb + 30720, tid);
    CP_COMMIT;
    stage_cp<128>(PE, HD, sb + 40960, tid);
    stage_cp<128>(PE + 32, HD, sb + 51200, tid);
    CP_COMMIT;

    cp_wait<1>();
    __syncthreads();

    // hoist Q fragments: [tm][kfrag 0..3] (kfrag = sub*2 + kk16)
    uint32_t af[2][4][4];
    #pragma unroll
    for (int tm = 0; tm < 2; tm++)
        #pragma unroll
        for (int kf = 0; kf < 4; kf++) {
            int sub = kf >> 1, kk = (kf & 1) * 16;
            int r = wm * 32 + tm * 16 + ((lane >> 3) & 1) * 8 + (lane & 7);
            int cc = kk + ((lane >> 4) & 1) * 8;
            ldm4(af[tm][kf], sb + sub * 10240 + (uint32_t)(r * 80 + cc * 2));
        }

    // ---- phase 1: logits ----
    {
        float acc[2][8][4] = {};
        #pragma unroll
        for (int kf = 0; kf < 4; kf++) {
            int sub = kf >> 1, kk = (kf & 1) * 16;
            #pragma unroll
            for (int p = 0; p < 4; p++) {
                uint32_t bh[4];
                int r = wn * 64 + p * 16 + ((lane >> 4) & 1) * 8 + (lane & 7);
                int cc = kk + ((lane >> 3) & 1) * 8;
                ldm4(bh, sb + 20480 + sub * 10240 + (uint32_t)(r * 80 + cc * 2));
                #pragma unroll
                for (int tm = 0; tm < 2; tm++) {
                    mma_f16(acc[tm][2 * p],     af[tm][kf], bh);
                    mma_f16(acc[tm][2 * p + 1], af[tm][kf], bh + 2);
                }
            }
        }
        __half* Lb = g_logits + ((size_t)hb << 20);
        #pragma unroll
        for (int tm = 0; tm < 2; tm++) {
            #pragma unroll
            for (int tn = 0; tn < 8; tn++) {
                int c = t0b + wn * 64 + tn * 8 + 2 * (lane & 3);
                #pragma unroll
                for (int half_ = 0; half_ < 2; half_++) {
                    int m = m0b + wm * 32 + tm * 16 + (lane >> 2) + half_ * 8;
                    __half2 v = __floats2half2_rn(acc[tm][tn][2 * half_ + 0] * 0.125f,
                                                  acc[tm][tn][2 * half_ + 1] * 0.125f);
                    stcs32(Lb + (size_t)m * SEQ + c, *(uint32_t*)&v);
                }
            }
        }
    }

    cp_wait<0>();
    __syncthreads();

    // ---- phase 2: li ----
    {
        float acc[2][8][4] = {};
        #pragma unroll
        for (int kf = 0; kf < 4; kf++) {
            int sub = kf >> 1, kk = (kf & 1) * 16;
            #pragma unroll
            for (int p = 0; p < 4; p++) {
                uint32_t bh[4];
                int r = wn * 64 + p * 16 + ((lane >> 4) & 1) * 8 + (lane & 7);
                int cc = kk + ((lane >> 3) & 1) * 8;
                ldm4(bh, sb + 40960 + sub * 10240 + (uint32_t)(r * 80 + cc * 2));
                #pragma unroll
                for (int tm = 0; tm < 2; tm++) {
                    mma_f16(acc[tm][2 * p],     af[tm][kf], bh);
                    mma_f16(acc[tm][2 * p + 1], af[tm][kf], bh + 2);
                }
            }
        }
        __half* Lb = g_li + ((size_t)hb << 20);
        #pragma unroll
        for (int tm = 0; tm < 2; tm++) {
            #pragma unroll
            for (int tn = 0; tn < 8; tn++) {
                int c = t0b + wn * 64 + tn * 8 + 2 * (lane & 3);
                #pragma unroll
                for (int half_ = 0; half_ < 2; half_++) {
                    int m = m0b + wm * 32 + tm * 16 + (lane >> 2) + half_ * 8;
                    __half2 v = __floats2half2_rn(acc[tm][tn][2 * half_ + 0],
                                                  acc[tm][tn][2 * half_ + 1]);
                    stcs32(Lb + (size_t)m * SEQ + c, *(uint32_t*)&v);
                }
            }
        }
    }
}

// ---------------------------------------------------------------------------
// K4: per-row CoPE + softmax; streaming loads; instruction-dieted.
// ---------------------------------------------------------------------------
__global__ __launch_bounds__(128) void cope_softmax()
{
    __shared__ __align__(16) __half s_li[SEQ];
    __shared__ float s_w[4];
    __shared__ float s_m[4];
    __shared__ float s_s[4];

    const size_t row = blockIdx.x;
    __half* L = g_logits + (row << 10);
    const __half* li = g_li + (row << 10);
    const int tid = threadIdx.x;
    const int lane = tid & 31, warp = tid >> 5;

    *(uint4*)(s_li + tid * 8) = ldcs128(li + tid * 8);

    float l[8];
    {
        uint4 u = ldcs128(L + tid * 8);
        const __half2* hp = (const __half2*)&u;
        #pragma unroll
        for (int i = 0; i < 4; i++) {
            float2 f = __half22float2(hp[i]);
            l[2 * i + 0] = f.x;
            l[2 * i + 1] = f.y;
        }
    }

    float su[8];
    {
        float g = sigmoidf_(l[7]); su[7] = g;
        #pragma unroll
        for (int j = 6; j >= 0; j--) su[j] = su[j + 1] + sigmoidf_(l[j]);
    }
    float total = su[0];

    float v = total;
    #pragma unroll
    for (int off = 1; off < 32; off <<= 1) {
        float n = __shfl_down_sync(0xffffffffu, v, off);
        if (lane + off < 32) v += n;
    }
    if (lane == 0) s_w[warp] = v;
    __syncthreads();

    float basew = 0.f;
    #pragma unroll
    for (int w = 0; w < 4; w++) if (w > warp) basew += s_w[w];
    float base = basew + (v - total);

    float m = -INFINITY;
    #pragma unroll
    for (int j = 0; j < 8; j++) {
        float p = fminf(base + su[j], 999.0f);
        float pf = floorf(p);
        float w = p - pf;
        int fi = (int)pf;
        float lf = __half2float(s_li[fi]);
        float lc = __half2float(s_li[fi + 1]);
        l[j] += lf + w * (lc - lf);
        m = fmaxf(m, l[j]);
    }

    #pragma unroll
    for (int off = 16; off; off >>= 1)
        m = fmaxf(m, __shfl_xor_sync(0xffffffffu, m, off));
    if (lane == 0) s_m[warp] = m;
    __syncthreads();
    m = fmaxf(fmaxf(s_m[0], s_m[1]), fmaxf(s_m[2], s_m[3]));

    const float L2E = 1.4426950408889634f;
    float nm = -m * L2E;
    float sum = 0.f;
    #pragma unroll
    for (int j = 0; j < 8; j++) {
        l[j] = ex2_(fmaf(l[j], L2E, nm));
        sum += l[j];
    }
    #pragma unroll
    for (int off = 16; off; off >>= 1)
        sum += __shfl_xor_sync(0xffffffffu, sum, off);
    if (lane == 0) s_s[warp] = sum;
    __syncthreads();
    float inv = __fdividef(1.0f, s_s[0] + s_s[1] + s_s[2] + s_s[3]);

    union { __half2 h2[4]; uint4 u; } pv;
    #pragma unroll
    for (int i = 0; i < 4; i++)
        pv.h2[i] = __floats2half2_rn(l[2 * i] * inv, l[2 * i + 1] * inv);
    *(uint4*)(gp + (row << 10) + tid * 8) = pv.u;
}

// ---------------------------------------------------------------------------
// K5: ctx = attn · V per (h,b). N = 64 -> fp16 ctx (3-stage, 64-k chunks)
// ---------------------------------------------------------------------------
__global__ __launch_bounds__(256, 2) void av_mma()
{
    extern __shared__ char smem[];
    const int tid = threadIdx.x;
    const int warp = tid >> 5, lane = tid & 31;
    const int wm = warp >> 1, wn = warp & 1;
    const int m0b = blockIdx.x * 128, hb = blockIdx.y;
    const int h = hb >> 2, b_ = hb & 3;

    float acc[2][4][4] = {};
    mma_core<4, 3>(gp + ((size_t)hb << 20) + (size_t)m0b * SEQ, SEQ,
                   gvt + (size_t)hb * HD * SEQ, SEQ,
                   SEQ, acc, smem);

    #pragma unroll
    for (int tm = 0; tm < 2; tm++) {
        #pragma unroll
        for (int tn = 0; tn < 4; tn++) {
            int d = wn * 32 + tn * 8 + 2 * (lane & 3);
            #pragma unroll
            for (int half_ = 0; half_ < 2; half_++) {
                int s = m0b + wm * 32 + tm * 16 + (lane >> 2) + half_ * 8;
                __half2 v = __floats2half2_rn(acc[tm][tn][2 * half_ + 0],
                                              acc[tm][tn][2 * half_ + 1]);
                *(__half2*)(gctx + ((size_t)s * BATCH + b_) * DM + h * HD + d) = v;
            }
        }
    }
}

// ---------------------------------------------------------------------------
// K6: output projection (+bias) -> fp32 out
// ---------------------------------------------------------------------------
__global__ __launch_bounds__(256, 2) void out_mma(const float* __restrict__ bo,
                                                  float* __restrict__ out)
{
    extern __shared__ char smem[];
    const int tid = threadIdx.x;
    const int warp = tid >> 5, lane = tid & 31;
    const int wm = warp >> 1, wn = warp & 1;
    const int n0b = blockIdx.x * 128, m0b = blockIdx.y * 128;

    float acc[2][8][4] = {};
    mma_core<8, 2>(gctx + (size_t)m0b * DM, DM,
                   gw + (size_t)3 * DM * DM + (size_t)n0b * DM, DM,
                   DM, acc, smem);

    #pragma unroll
    for (int tm = 0; tm < 2; tm++) {
        #pragma unroll
        for (int tn = 0; tn < 8; tn++) {
            int c = n0b + wn * 64 + tn * 8 + 2 * (lane & 3);
            float2 bb = *(const float2*)(bo + c);
            #pragma unroll
            for (int half_ = 0; half_ < 2; half_++) {
                int m = m0b + wm * 32 + tm * 16 + (lane >> 2) + half_ * 8;
                float2 v;
                v.x = acc[tm][tn][2 * half_ + 0] + bb.x;
                v.y = acc[tm][tn][2 * half_ + 1] + bb.y;
                *(float2*)(out + (size_t)m * DM + c) = v;
            }
        }
    }
}

// ---------------------------------------------------------------------------
extern "C" void kernel_launch(void* const* d_in, const int* in_sizes, int n_in,
                              void* d_out, int out_size)
{
    const float* x  = (const float*)d_in[0];
    const float* Wq = (const float*)d_in[1];
    const float* bq = (const float*)d_in[2];
    const float* Wk = (const float*)d_in[3];
    const float* bk = (const float*)d_in[4];
    const float* Wv = (const float*)d_in[5];
    const float* bv = (const float*)d_in[6];
    const float* Wo = (const float*)d_in[7];
    const float* bo = (const float*)d_in[8];
    const float* pe = (const float*)d_in[9];
    float* out = (float*)d_out;

    cudaFuncSetAttribute(qkv_mma,   cudaFuncAttributeMaxDynamicSharedMemorySize, SMEM_N128);
    cudaFuncSetAttribute(out_mma,   cudaFuncAttributeMaxDynamicSharedMemorySize, SMEM_N128);
    cudaFuncSetAttribute(qkqpe_mma, cudaFuncAttributeMaxDynamicSharedMemorySize, SMEM_QKPE);
    cudaFuncSetAttribute(av_mma,    cudaFuncAttributeMaxDynamicSharedMemorySize, SMEM_AV);

    prologue_conv<<<dim3(DM / 32, DM / 32, 6), 256>>>(Wq, Wk, Wv, Wo, pe, x);

    qkv_mma<<<dim3(DM / 128, NTOK / 128, 3), 256, SMEM_N128>>>(bq, bk, bv);

    transpose_v<<<dim3(SEQ / 32, HD / 32, NHB), 256>>>();

    qkqpe_mma<<<dim3(SEQ / 128, SEQ / 128, NHB), 256, SMEM_QKPE>>>();

    cope_softmax<<<NHB * SEQ, 128>>>();

    av_mma<<<dim3(SEQ / 128, NHB), 256, SMEM_AV>>>();

    out_mma<<<dim3(DM / 128, NTOK / 128), 256, SMEM_N128>>>(bo, out);
}

// round 17
// speedup vs baseline: 1.4770x; 1.0664x over previous
#include <cuda_runtime.h>
#include <cuda_fp16.h>
#include <math.h>
#include <stdint.h>

#define SEQ   1024
#define BATCH 4
#define DM    1024
#define NH    16
#define HD    64
#define NPOS  1000
#define NTOK  (SEQ*BATCH)   // 4096
#define NHB   (NH*BATCH)    // 64

// ---------------------------------------------------------------------------
// Device scratch (no runtime allocation allowed) — all fp16
// ---------------------------------------------------------------------------
__device__ __align__(16) __half gx[NTOK*DM];
__device__ __align__(16) __half gw[4*DM*DM];          // WqT,WkT,WvT,WoT [n][k]
__device__ __align__(16) __half gpet[SEQ*HD];         // peT [n pad][d]
__device__ __align__(16) __half gq[NHB*SEQ*HD];
__device__ __align__(16) __half gk[NHB*SEQ*HD];
__device__ __align__(16) __half gv[NHB*SEQ*HD];
__device__ __align__(16) __half gvt[NHB*HD*SEQ];      // vT [hb][d][t]
__device__ __align__(16) __half g_logits[(size_t)NHB*SEQ*SEQ];  // 134 MB
__device__ __align__(16) __half g_li[(size_t)NHB*SEQ*SEQ];      // 134 MB
__device__ __align__(16) __half gp[(size_t)NHB*SEQ*SEQ];        // probs
__device__ __align__(16) __half gctx[NTOK*DM];

// ---------------------------------------------------------------------------
// Helpers (baseline PTX only)
// ---------------------------------------------------------------------------
__device__ __forceinline__ uint32_t smem_u32(const void* p) {
    uint32_t a;
    asm("{ .reg .u64 t; cvta.to.shared.u64 t, %1; cvt.u32.u64 %0, t; }"
        : "=r"(a) : "l"(p));
    return a;
}
__device__ __forceinline__ void ldm4(uint32_t* r, uint32_t addr) {
    asm volatile("ldmatrix.sync.aligned.m8n8.x4.shared.b16 {%0,%1,%2,%3}, [%4];"
        : "=r"(r[0]), "=r"(r[1]), "=r"(r[2]), "=r"(r[3]) : "r"(addr));
}
__device__ __forceinline__ void mma_f16(float* c, const uint32_t* a,
                                        const uint32_t* b) {
    asm volatile(
        "mma.sync.aligned.m16n8k16.row.col.f32.f16.f16.f32 "
        "{%0,%1,%2,%3}, {%4,%5,%6,%7}, {%8,%9}, {%0,%1,%2,%3};"
        : "+f"(c[0]), "+f"(c[1]), "+f"(c[2]), "+f"(c[3])
        : "r"(a[0]), "r"(a[1]), "r"(a[2]), "r"(a[3]), "r"(b[0]), "r"(b[1]));
}
__device__ __forceinline__ void cp16(uint32_t dst, const void* src) {
    asm volatile("cp.async.ca.shared.global [%0], [%1], 16;"
                 :: "r"(dst), "l"(src));
}
#define CP_COMMIT asm volatile("cp.async.commit_group;" ::: "memory")
template<int N>
__device__ __forceinline__ void cp_wait() {
    asm volatile("cp.async.wait_group %0;" :: "n"(N) : "memory");
}
// streaming (evict-first) stores / loads
__device__ __forceinline__ void stcs32(void* p, uint32_t v) {
    asm volatile("st.global.cs.b32 [%0], %1;" :: "l"(p), "r"(v) : "memory");
}
__device__ __forceinline__ void stcs128(void* p, uint4 v) {
    asm volatile("st.global.cs.v4.b32 [%0], {%1,%2,%3,%4};"
                 :: "l"(p), "r"(v.x), "r"(v.y), "r"(v.z), "r"(v.w) : "memory");
}
__device__ __forceinline__ uint4 ldcs128(const void* p) {
    uint4 r;
    asm volatile("ld.global.cs.v4.b32 {%0,%1,%2,%3}, [%4];"
        : "=r"(r.x), "=r"(r.y), "=r"(r.z), "=r"(r.w) : "l"(p));
    return r;
}

__device__ __forceinline__ float ex2_(float x) {
    float r;
    asm("ex2.approx.f32 %0, %1;" : "=f"(r) : "f"(x));
    return r;
}
__device__ __forceinline__ float sigmoidf_(float x) {
    return __fdividef(1.0f, 1.0f + __expf(-x));
}

// ---------------------------------------------------------------------------
// Stage ROWSx32 fp16 K-major subtile via cp.async; pitch 80B.
// ---------------------------------------------------------------------------
template<int ROWS>
__device__ __forceinline__ void stage_cp(const __half* __restrict__ src, int ld,
                                         uint32_t smem_byte, int tid)
{
    #pragma unroll
    for (int it = 0; it < ROWS / 64; it++) {
        int q = tid + it * 256;
        int row = q >> 2, ch = q & 3;
        cp16(smem_byte + row * 80 + ch * 16, src + (size_t)row * ld + ch * 8);
    }
}

// ---------------------------------------------------------------------------
// Core: C[128 x NTILE*16] += A[128 x ktot] · B[NTILE*16 x ktot]^T
// fp16 single-product, fp32 accum. 64-k chunks (two 32-k subtiles per stage),
// STAGES-deep cp.async ring, ONE sync per 64-k chunk. 8 warps as 4(m) x 2(n).
// ---------------------------------------------------------------------------
template<int NTILE, int STAGES>
__device__ __forceinline__ void mma_core(
    const __half* A, int a_ld, const __half* B, int b_ld,
    int ktot, float acc[2][NTILE][4], char* smem)
{
    const int tid = threadIdx.x;
    const int warp = tid >> 5, lane = tid & 31;
    const int wm = warp >> 1, wn = warp & 1;
    constexpr int NROWS = NTILE * 16;
    constexpr int TA32 = 128 * 80;
    constexpr int TB32 = NROWS * 80;
    constexpr int TA = 2 * TA32;
    constexpr int TB = 2 * TB32;
    constexpr int STAGE = TA + TB;
    const uint32_t sb = smem_u32(smem);
    const int nch = ktot / 64;

    #pragma unroll
    for (int s = 0; s < STAGES - 1; s++) {
        if (s < nch) {
            uint32_t nb = sb + s * STAGE;
            stage_cp<128>(A + s * 64, a_ld, nb, tid);
            stage_cp<128>(A + s * 64 + 32, a_ld, nb + TA32, tid);
            stage_cp<NROWS>(B + s * 64, b_ld, nb + TA, tid);
            stage_cp<NROWS>(B + s * 64 + 32, b_ld, nb + TA + TB32, tid);
        }
        CP_COMMIT;
    }

    for (int c = 0; c < nch; c++) {
        cp_wait<STAGES - 2>();
        __syncthreads();
        int pf = c + STAGES - 1;
        if (pf < nch) {
            uint32_t nb = sb + (pf % STAGES) * STAGE;
            stage_cp<128>(A + pf * 64, a_ld, nb, tid);
            stage_cp<128>(A + pf * 64 + 32, a_ld, nb + TA32, tid);
            stage_cp<NROWS>(B + pf * 64, b_ld, nb + TA, tid);
            stage_cp<NROWS>(B + pf * 64 + 32, b_ld, nb + TA + TB32, tid);
        }
        CP_COMMIT;

        const uint32_t cb = sb + (c % STAGES) * STAGE;
        #pragma unroll
        for (int sub = 0; sub < 2; sub++) {
            const uint32_t ca = cb + sub * TA32;
            const uint32_t cbB = cb + TA + sub * TB32;
            #pragma unroll
            for (int kk = 0; kk < 32; kk += 16) {
                uint32_t ah[2][4];
                #pragma unroll
                for (int tm = 0; tm < 2; tm++) {
                    int r = wm * 32 + tm * 16 + ((lane >> 3) & 1) * 8 + (lane & 7);
                    int cc = kk + ((lane >> 4) & 1) * 8;
                    ldm4(ah[tm], ca + (uint32_t)(r * 80 + cc * 2));
                }
                #pragma unroll
                for (int p = 0; p < NTILE / 2; p++) {
                    uint32_t bh[4];
                    int r = wn * NTILE * 8 + p * 16 + ((lane >> 4) & 1) * 8 + (lane & 7);
                    int cc = kk + ((lane >> 3) & 1) * 8;
                    ldm4(bh, cbB + (uint32_t)(r * 80 + cc * 2));
                    #pragma unroll
                    for (int tm = 0; tm < 2; tm++) {
                        mma_f16(acc[tm][2 * p],     ah[tm], bh);
                        mma_f16(acc[tm][2 * p + 1], ah[tm], bh + 2);
                    }
                }
            }
        }
    }
}

#define SMEM_N128 (2 * (2 * 128 * 80 + 2 * 128 * 80))   // 81920 (2-stage, N128)
#define SMEM_AV   (3 * (2 * 128 * 80 + 2 * 64 * 80))    // 92160 (3-stage, N64)
#define SMEM_QKPE (6 * 128 * 80)                        // 61440 (Q + Bk + Bpe)

// ---------------------------------------------------------------------------
// Prologue: z=0..3 W transposes; z=4 pe transpose (y<2); z=5 convert_x
// ---------------------------------------------------------------------------
__global__ __launch_bounds__(256) void prologue_conv(
    const float* __restrict__ Wq, const float* __restrict__ Wk,
    const float* __restrict__ Wv, const float* __restrict__ Wo,
    const float* __restrict__ pe, const float* __restrict__ x)
{
    __shared__ float t[32][33];
    int tx = threadIdx.x & 31, ty = threadIdx.x >> 5;
    int bx = blockIdx.x * 32, by = blockIdx.y * 32;
    int z = blockIdx.z;

    if (z < 4) {
        const float* W = (z == 0) ? Wq : (z == 1) ? Wk : (z == 2) ? Wv : Wo;
        size_t base = (size_t)z * DM * DM;
        #pragma unroll
        for (int j = 0; j < 4; j++)
            t[ty + 8 * j][tx] = W[(size_t)(by + ty + 8 * j) * DM + bx + tx];
        __syncthreads();
        #pragma unroll
        for (int j = 0; j < 4; j++)
            gw[base + (size_t)(bx + ty + 8 * j) * DM + by + tx] =
                __float2half_rn(t[tx][ty + 8 * j]);
    } else if (z == 4) {
        if (by >= HD) return;
        #pragma unroll
        for (int j = 0; j < 4; j++) {
            int d = by + ty + 8 * j, n = bx + tx;
            t[ty + 8 * j][tx] = (n < NPOS) ? pe[(size_t)d * NPOS + n] : 0.0f;
        }
        __syncthreads();
        #pragma unroll
        for (int j = 0; j < 4; j++)
            gpet[(size_t)(bx + ty + 8 * j) * HD + by + tx] =
                __float2half_rn(t[tx][ty + 8 * j]);
    } else {
        int blk = blockIdx.y * 32 + blockIdx.x;
        size_t i0 = (size_t)blk * 4096 + threadIdx.x * 4;
        #pragma unroll
        for (int it = 0; it < 4; it++) {
            size_t i = i0 + it * 1024;
            float4 v = *(const float4*)(x + i);
            *(__half2*)(gx + i)     = __floats2half2_rn(v.x, v.y);
            *(__half2*)(gx + i + 2) = __floats2half2_rn(v.z, v.w);
        }
    }
}

__global__ __launch_bounds__(256) void transpose_v()
{
    __shared__ __half t[32][40];
    int hb = blockIdx.z;
    const __half* V = gv + (size_t)hb * SEQ * HD;
    size_t base = (size_t)hb * HD * SEQ;
    int tx = threadIdx.x & 31, ty = threadIdx.x >> 5;
    int bx = blockIdx.x * 32, by = blockIdx.y * 32;   // bx: t, by: d
    #pragma unroll
    for (int j = 0; j < 4; j++)
        t[ty + 8 * j][tx] = V[(size_t)(bx + ty + 8 * j) * HD + by + tx];
    __syncthreads();
    #pragma unroll
    for (int j = 0; j < 4; j++)
        gvt[base + (size_t)(by + ty + 8 * j) * SEQ + bx + tx] = t[tx][ty + 8 * j];
}

// ---------------------------------------------------------------------------
// K1: QKV projections (scatter to head layout, +bias) -> fp16 q,k,v
// ---------------------------------------------------------------------------
__global__ __launch_bounds__(256, 2) void qkv_mma(
    const float* __restrict__ bq, const float* __restrict__ bk,
    const float* __restrict__ bv)
{
    extern __shared__ char smem[];
    const int tid = threadIdx.x;
    const int warp = tid >> 5, lane = tid & 31;
    const int wm = warp >> 1, wn = warp & 1;
    const int n0b = blockIdx.x * 128, m0b = blockIdx.y * 128, z = blockIdx.z;
    const float* bias = (z == 0) ? bq : (z == 1) ? bk : bv;
    __half* out = (z == 0) ? gq : (z == 1) ? gk : gv;

    float acc[2][8][4] = {};
    mma_core<8, 2>(gx + (size_t)m0b * DM, DM,
                   gw + (size_t)z * DM * DM + (size_t)n0b * DM, DM,
                   DM, acc, smem);

    #pragma unroll
    for (int tm = 0; tm < 2; tm++) {
        #pragma unroll
        for (int tn = 0; tn < 8; tn++) {
            int c = n0b + wn * 64 + tn * 8 + 2 * (lane & 3);
            int h = c >> 6, d = c & 63;
            float2 bb = *(const float2*)(bias + c);
            #pragma unroll
            for (int half_ = 0; half_ < 2; half_++) {
                int m = m0b + wm * 32 + tm * 16 + (lane >> 2) + half_ * 8;
                int s = m >> 2, b_ = m & 3;
                __half2 v = __floats2half2_rn(acc[tm][tn][2 * half_ + 0] + bb.x,
                                              acc[tm][tn][2 * half_ + 1] + bb.y);
                *(__half2*)(out + ((size_t)(h * BATCH + b_) * SEQ + s) * HD + d) = v;
            }
        }
    }
}

// ---------------------------------------------------------------------------
// Coalesced tile store via smem staging (pitch 272B, conflict-free).
// Writes acc (scaled -> fp16) to Lb[(m0b..+127) x (t0b..+127)] with
// fully-coalesced 128-bit streaming stores.
// ---------------------------------------------------------------------------
__device__ __forceinline__ void store_tile_coalesced(
    float acc[2][8][4], char* stage, __half* Lb,
    int m0b, int t0b, float scale, int tid, int wm, int wn, int lane)
{
    #pragma unroll
    for (int tm = 0; tm < 2; tm++) {
        #pragma unroll
        for (int tn = 0; tn < 8; tn++) {
            int c = wn * 64 + tn * 8 + 2 * (lane & 3);
            #pragma unroll
            for (int half_ = 0; half_ < 2; half_++) {
                int r = wm * 32 + tm * 16 + (lane >> 2) + half_ * 8;
                __half2 v = __floats2half2_rn(acc[tm][tn][2 * half_ + 0] * scale,
                                              acc[tm][tn][2 * half_ + 1] * scale);
                *(__half2*)(stage + r * 272 + c * 2) = v;
            }
        }
    }
    __syncthreads();
    #pragma unroll
    for (int it = 0; it < 8; it++) {
        int r = it * 16 + (tid >> 4);
        int ch = tid & 15;
        uint4 v = *(const uint4*)(stage + r * 272 + ch * 16);
        stcs128(Lb + (size_t)(m0b + r) * SEQ + t0b + ch * 8, v);
    }
}

// ---------------------------------------------------------------------------
// K2 (merged): one CTA per (hb, m-tile, t-tile) computes BOTH
// logits = 0.125*Q·K^T and li = Q·PE^T. Q staged+fragmented once.
// Epilogues staged through smem for fully-coalesced streaming stores.
// smem: Q [0,20480) ; Bk [20480,40960) ; Bpe [40960,61440)
// staging reuses [0,34816) after MMAs of each phase.
// ---------------------------------------------------------------------------
__global__ __launch_bounds__(256, 2) void qkqpe_mma()
{
    extern __shared__ char smem[];
    const int tid = threadIdx.x;
    const int warp = tid >> 5, lane = tid & 31;
    const int wm = warp >> 1, wn = warp & 1;
    const int t0b = blockIdx.x * 128, m0b = blockIdx.y * 128, hb = blockIdx.z;
    const uint32_t sb = smem_u32(smem);

    const __half* Q  = gq + (size_t)hb * SEQ * HD + (size_t)m0b * HD;
    const __half* K  = gk + (size_t)hb * SEQ * HD + (size_t)t0b * HD;
    const __half* PE = gpet + (size_t)t0b * HD;

    stage_cp<128>(Q, HD, sb, tid);
    stage_cp<128>(Q + 32, HD, sb + 10240, tid);
    stage_cp<128>(K, HD, sb + 20480, tid);
    stage_cp<128>(K + 32, HD, sb + 30720, tid);
    CP_COMMIT;
    stage_cp<128>(PE, HD, sb + 40960, tid);
    stage_cp<128>(PE + 32, HD, sb + 51200, tid);
    CP_COMMIT;

    cp_wait<1>();
    __syncthreads();

    // hoist Q fragments: [tm][kfrag 0..3] (kfrag = sub*2 + kk16)
    uint32_t af[2][4][4];
    #pragma unroll
    for (int tm = 0; tm < 2; tm++)
        #pragma unroll
        for (int kf = 0; kf < 4; kf++) {
            int sub = kf >> 1, kk = (kf & 1) * 16;
            int r = wm * 32 + tm * 16 + ((lane >> 3) & 1) * 8 + (lane & 7);
            int cc = kk + ((lane >> 4) & 1) * 8;
            ldm4(af[tm][kf], sb + sub * 10240 + (uint32_t)(r * 80 + cc * 2));
        }

    // ---- phase 1: logits ----
    {
        float acc[2][8][4] = {};
        #pragma unroll
        for (int kf = 0; kf < 4; kf++) {
            int sub = kf >> 1, kk = (kf & 1) * 16;
            #pragma unroll
            for (int p = 0; p < 4; p++) {
                uint32_t bh[4];
                int r = wn * 64 + p * 16 + ((lane >> 4) & 1) * 8 + (lane & 7);
                int cc = kk + ((lane >> 3) & 1) * 8;
                ldm4(bh, sb + 20480 + sub * 10240 + (uint32_t)(r * 80 + cc * 2));
                #pragma unroll
                for (int tm = 0; tm < 2; tm++) {
                    mma_f16(acc[tm][2 * p],     af[tm][kf], bh);
                    mma_f16(acc[tm][2 * p + 1], af[tm][kf], bh + 2);
                }
            }
        }
        __syncthreads();   // all warps done reading Q/Bk smem
        store_tile_coalesced(acc, smem, g_logits + ((size_t)hb << 20),
                             m0b, t0b, 0.125f, tid, wm, wn, lane);
    }

    cp_wait<0>();
    __syncthreads();

    // ---- phase 2: li ----
    {
        float acc[2][8][4] = {};
        #pragma unroll
        for (int kf = 0; kf < 4; kf++) {
            int sub = kf >> 1, kk = (kf & 1) * 16;
            #pragma unroll
            for (int p = 0; p < 4; p++) {
                uint32_t bh[4];
                int r = wn * 64 + p * 16 + ((lane >> 4) & 1) * 8 + (lane & 7);
                int cc = kk + ((lane >> 3) & 1) * 8;
                ldm4(bh, sb + 40960 + sub * 10240 + (uint32_t)(r * 80 + cc * 2));
                #pragma unroll
                for (int tm = 0; tm < 2; tm++) {
                    mma_f16(acc[tm][2 * p],     af[tm][kf], bh);
                    mma_f16(acc[tm][2 * p + 1], af[tm][kf], bh + 2);
                }
            }
        }
        __syncthreads();   // all warps done with phase-1 staging reads
        store_tile_coalesced(acc, smem, g_li + ((size_t)hb << 20),
                             m0b, t0b, 1.0f, tid, wm, wn, lane);
    }
}

// ---------------------------------------------------------------------------
// K4: per-row CoPE + softmax; streaming loads; instruction-dieted.
// ---------------------------------------------------------------------------
__global__ __launch_bounds__(128) void cope_softmax()
{
    __shared__ __align__(16) __half s_li[SEQ];
    __shared__ float s_w[4];
    __shared__ float s_m[4];
    __shared__ float s_s[4];

    const size_t row = blockIdx.x;
    __half* L = g_logits + (row << 10);
    const __half* li = g_li + (row << 10);
    const int tid = threadIdx.x;
    const int lane = tid & 31, warp = tid >> 5;

    *(uint4*)(s_li + tid * 8) = ldcs128(li + tid * 8);

    float l[8];
    {
        uint4 u = ldcs128(L + tid * 8);
        const __half2* hp = (const __half2*)&u;
        #pragma unroll
        for (int i = 0; i < 4; i++) {
            float2 f = __half22float2(hp[i]);
            l[2 * i + 0] = f.x;
            l[2 * i + 1] = f.y;
        }
    }

    float su[8];
    {
        float g = sigmoidf_(l[7]); su[7] = g;
        #pragma unroll
        for (int j = 6; j >= 0; j--) su[j] = su[j + 1] + sigmoidf_(l[j]);
    }
    float total = su[0];

    float v = total;
    #pragma unroll
    for (int off = 1; off < 32; off <<= 1) {
        float n = __shfl_down_sync(0xffffffffu, v, off);
        if (lane + off < 32) v += n;
    }
    if (lane == 0) s_w[warp] = v;
    __syncthreads();

    float basew = 0.f;
    #pragma unroll
    for (int w = 0; w < 4; w++) if (w > warp) basew += s_w[w];
    float base = basew + (v - total);

    float m = -INFINITY;
    #pragma unroll
    for (int j = 0; j < 8; j++) {
        float p = fminf(base + su[j], 999.0f);
        float pf = floorf(p);
        float w = p - pf;
        int fi = (int)pf;
        float lf = __half2float(s_li[fi]);
        float lc = __half2float(s_li[fi + 1]);
        l[j] += lf + w * (lc - lf);
        m = fmaxf(m, l[j]);
    }

    #pragma unroll
    for (int off = 16; off; off >>= 1)
        m = fmaxf(m, __shfl_xor_sync(0xffffffffu, m, off));
    if (lane == 0) s_m[warp] = m;
    __syncthreads();
    m = fmaxf(fmaxf(s_m[0], s_m[1]), fmaxf(s_m[2], s_m[3]));

    const float L2E = 1.4426950408889634f;
    float nm = -m * L2E;
    float sum = 0.f;
    #pragma unroll
    for (int j = 0; j < 8; j++) {
        l[j] = ex2_(fmaf(l[j], L2E, nm));
        sum += l[j];
    }
    #pragma unroll
    for (int off = 16; off; off >>= 1)
        sum += __shfl_xor_sync(0xffffffffu, sum, off);
    if (lane == 0) s_s[warp] = sum;
    __syncthreads();
    float inv = __fdividef(1.0f, s_s[0] + s_s[1] + s_s[2] + s_s[3]);

    union { __half2 h2[4]; uint4 u; } pv;
    #pragma unroll
    for (int i = 0; i < 4; i++)
        pv.h2[i] = __floats2half2_rn(l[2 * i] * inv, l[2 * i + 1] * inv);
    *(uint4*)(gp + (row << 10) + tid * 8) = pv.u;
}

// ---------------------------------------------------------------------------
// K5: ctx = attn · V per (h,b). N = 64 -> fp16 ctx (3-stage, 64-k chunks)
// ---------------------------------------------------------------------------
__global__ __launch_bounds__(256, 2) void av_mma()
{
    extern __shared__ char smem[];
    const int tid = threadIdx.x;
    const int warp = tid >> 5, lane = tid & 31;
    const int wm = warp >> 1, wn = warp & 1;
    const int m0b = blockIdx.x * 128, hb = blockIdx.y;
    const int h = hb >> 2, b_ = hb & 3;

    float acc[2][4][4] = {};
    mma_core<4, 3>(gp + ((size_t)hb << 20) + (size_t)m0b * SEQ, SEQ,
                   gvt + (size_t)hb * HD * SEQ, SEQ,
                   SEQ, acc, smem);

    #pragma unroll
    for (int tm = 0; tm < 2; tm++) {
        #pragma unroll
        for (int tn = 0; tn < 4; tn++) {
            int d = wn * 32 + tn * 8 + 2 * (lane & 3);
            #pragma unroll
            for (int half_ = 0; half_ < 2; half_++) {
                int s = m0b + wm * 32 + tm * 16 + (lane >> 2) + half_ * 8;
                __half2 v = __floats2half2_rn(acc[tm][tn][2 * half_ + 0],
                                              acc[tm][tn][2 * half_ + 1]);
                *(__half2*)(gctx + ((size_t)s * BATCH + b_) * DM + h * HD + d) = v;
            }
        }
    }
}

// ---------------------------------------------------------------------------
// K6: output projection (+bias) -> fp32 out
// ---------------------------------------------------------------------------
__global__ __launch_bounds__(256, 2) void out_mma(const float* __restrict__ bo,
                                                  float* __restrict__ out)
{
    extern __shared__ char smem[];
    const int tid = threadIdx.x;
    const int warp = tid >> 5, lane = tid & 31;
    const int wm = warp >> 1, wn = warp & 1;
    const int n0b = blockIdx.x * 128, m0b = blockIdx.y * 128;

    float acc[2][8][4] = {};
    mma_core<8, 2>(gctx + (size_t)m0b * DM, DM,
                   gw + (size_t)3 * DM * DM + (size_t)n0b * DM, DM,
                   DM, acc, smem);

    #pragma unroll
    for (int tm = 0; tm < 2; tm++) {
        #pragma unroll
        for (int tn = 0; tn < 8; tn++) {
            int c = n0b + wn * 64 + tn * 8 + 2 * (lane & 3);
            float2 bb = *(const float2*)(bo + c);
            #pragma unroll
            for (int half_ = 0; half_ < 2; half_++) {
                int m = m0b + wm * 32 + tm * 16 + (lane >> 2) + half_ * 8;
                float2 v;
                v.x = acc[tm][tn][2 * half_ + 0] + bb.x;
                v.y = acc[tm][tn][2 * half_ + 1] + bb.y;
                *(float2*)(out + (size_t)m * DM + c) = v;
            }
        }
    }
}

// ---------------------------------------------------------------------------
extern "C" void kernel_launch(void* const* d_in, const int* in_sizes, int n_in,
                              void* d_out, int out_size)
{
    const float* x  = (const float*)d_in[0];
    const float* Wq = (const float*)d_in[1];
    const float* bq = (const float*)d_in[2];
    const float* Wk = (const float*)d_in[3];
    const float* bk = (const float*)d_in[4];
    const float* Wv = (const float*)d_in[5];
    const float* bv = (const float*)d_in[6];
    const float* Wo = (const float*)d_in[7];
    const float* bo = (const float*)d_in[8];
    const float* pe = (const float*)d_in[9];
    float* out = (float*)d_out;

    cudaFuncSetAttribute(qkv_mma,   cudaFuncAttributeMaxDynamicSharedMemorySize, SMEM_N128);
    cudaFuncSetAttribute(out_mma,   cudaFuncAttributeMaxDynamicSharedMemorySize, SMEM_N128);
    cudaFuncSetAttribute(qkqpe_mma, cudaFuncAttributeMaxDynamicSharedMemorySize, SMEM_QKPE);
    cudaFuncSetAttribute(av_mma,    cudaFuncAttributeMaxDynamicSharedMemorySize, SMEM_AV);

    prologue_conv<<<dim3(DM / 32, DM / 32, 6), 256>>>(Wq, Wk, Wv, Wo, pe, x);

    qkv_mma<<<dim3(DM / 128, NTOK / 128, 3), 256, SMEM_N128>>>(bq, bk, bv);

    transpose_v<<<dim3(SEQ / 32, HD / 32, NHB), 256>>>();

    qkqpe_mma<<<dim3(SEQ / 128, SEQ / 128, NHB), 256, SMEM_QKPE>>>();

    cope_softmax<<<NHB * SEQ, 128>>>();

    av_mma<<<dim3(SEQ / 128, NHB), 256, SMEM_AV>>>();

    out_mma<<<dim3(DM / 128, NTOK / 128), 256, SMEM_N128>>>(bo, out);
}